// round 1
// baseline (speedup 1.0000x reference)
#include <cuda_runtime.h>

#define NHEAD  16
#define DMODEL 1024
#define HDIM   64
#define BATCH  2
#define SEQ    2048
#define MTOT   (BATCH*SEQ)   // 4096

// Scratch (device globals: allocation-free per harness rules)
__device__ float g_qp[MTOT*DMODEL];
__device__ float g_kp[MTOT*DMODEL];
__device__ float g_vp[MTOT*DMODEL];
__device__ float g_ctx[MTOT*DMODEL];

// ---------------------------------------------------------------------------
// SGEMM body: C[M,N] = A[M,K] @ W[K,N] + bias    (M=4096, N=K=1024)
// 64x64 tile, BK=16, 256 threads, 4x4 per thread, float4 smem reads.
// ---------------------------------------------------------------------------
__device__ __forceinline__ void gemm_body(const float* __restrict__ A,
                                          const float* __restrict__ W,
                                          const float* __restrict__ bias,
                                          float* __restrict__ C)
{
    __shared__ float As[16][68];   // As[k][m], padded, rows 16B-aligned
    __shared__ float Ws[16][68];   // Ws[k][n]

    const int tid = threadIdx.x;
    const int tx = tid & 15;
    const int ty = tid >> 4;
    const int m0 = blockIdx.y * 64;
    const int n0 = blockIdx.x * 64;

    float acc[4][4];
#pragma unroll
    for (int i = 0; i < 4; i++)
#pragma unroll
        for (int j = 0; j < 4; j++) acc[i][j] = 0.f;

    const int lka = tid & 15;   // A-load: k
    const int lma = tid >> 4;   // A-load: m base
    const int lnw = tid & 63;   // W-load: n
    const int lkw = tid >> 6;   // W-load: k base (0..3)

    for (int k0 = 0; k0 < DMODEL; k0 += 16) {
#pragma unroll
        for (int i = 0; i < 4; i++)
            As[lka][lma + i*16] = A[(size_t)(m0 + lma + i*16)*DMODEL + k0 + lka];
#pragma unroll
        for (int i = 0; i < 4; i++)
            Ws[lkw + i*4][lnw] = W[(size_t)(k0 + lkw + i*4)*DMODEL + n0 + lnw];
        __syncthreads();

#pragma unroll
        for (int kk = 0; kk < 16; kk++) {
            float4 a = *reinterpret_cast<const float4*>(&As[kk][ty*4]);
            float4 b = *reinterpret_cast<const float4*>(&Ws[kk][tx*4]);
            float av[4] = {a.x, a.y, a.z, a.w};
            float bv[4] = {b.x, b.y, b.z, b.w};
#pragma unroll
            for (int i = 0; i < 4; i++)
#pragma unroll
                for (int j = 0; j < 4; j++)
                    acc[i][j] += av[i] * bv[j];
        }
        __syncthreads();
    }

    float4 bb = *reinterpret_cast<const float4*>(&bias[n0 + tx*4]);
#pragma unroll
    for (int i = 0; i < 4; i++) {
        int m = m0 + ty*4 + i;
        float4 o;
        o.x = acc[i][0] + bb.x;
        o.y = acc[i][1] + bb.y;
        o.z = acc[i][2] + bb.z;
        o.w = acc[i][3] + bb.w;
        *reinterpret_cast<float4*>(&C[(size_t)m*DMODEL + n0 + tx*4]) = o;
    }
}

__global__ void gemm_qkv_kernel(const float* __restrict__ q,
                                const float* __restrict__ k,
                                const float* __restrict__ v,
                                const float* __restrict__ wq, const float* __restrict__ bq,
                                const float* __restrict__ wk, const float* __restrict__ bk,
                                const float* __restrict__ wv, const float* __restrict__ bv)
{
    const int which = blockIdx.z;
    const float* A    = (which == 0) ? q  : (which == 1) ? k  : v;
    const float* W    = (which == 0) ? wq : (which == 1) ? wk : wv;
    const float* bias = (which == 0) ? bq : (which == 1) ? bk : bv;
    float* C          = (which == 0) ? g_qp : (which == 1) ? g_kp : g_vp;
    gemm_body(A, W, bias, C);
}

__global__ void gemm_o_kernel(const float* __restrict__ wo,
                              const float* __restrict__ bo,
                              float* __restrict__ out)
{
    gemm_body(g_ctx, wo, bo, out);
}

// ---------------------------------------------------------------------------
// Flash attention (fp32, online softmax). Grid: (SEQ/64, BATCH*NHEAD), 256 thr.
// Block handles 64 query rows for one (b,h); loops over K in tiles of 32.
// Thread t: row = t>>2, quad = t&3; owns 8 score cols and 16 output cols.
// ---------------------------------------------------------------------------
__global__ __launch_bounds__(256) void attn_kernel(const int* __restrict__ mask)
{
    __shared__ float Qs[64][68];
    __shared__ float Ks[32][68];
    __shared__ float Vs[32][68];
    __shared__ float Ps[64][33];

    const int qb = blockIdx.x;
    const int bh = blockIdx.y;
    const int b  = bh / NHEAD;
    const int h  = bh % NHEAD;
    const int t  = threadIdx.x;
    const int row  = t >> 2;
    const int quad = t & 3;
    const int q0 = qb * 64;

    const float inv = 1.0f / (sqrtf((float)HDIM) + 1e-8f);

    // ---- load Q tile (64x64) as float4
    {
        const int dq = (t & 15) * 4;
        const int r  = t >> 4;          // 0..15
        const float* Qg = g_qp + ((size_t)(b*SEQ + q0))*DMODEL + h*HDIM;
#pragma unroll
        for (int i = 0; i < 4; i++) {
            float4 x = *reinterpret_cast<const float4*>(&Qg[(size_t)(r + i*16)*DMODEL + dq]);
            *reinterpret_cast<float4*>(&Qs[r + i*16][dq]) = x;
        }
    }

    float m = -1e30f, l = 0.f;
    float4 acc[4];
#pragma unroll
    for (int u = 0; u < 4; u++) acc[u] = make_float4(0.f, 0.f, 0.f, 0.f);

    const int* maskrow = mask + ((size_t)b*SEQ + (q0 + row)) * SEQ;
    const float* Kg = g_kp + ((size_t)(b*SEQ))*DMODEL + h*HDIM;
    const float* Vg = g_vp + ((size_t)(b*SEQ))*DMODEL + h*HDIM;

    for (int kb = 0; kb < SEQ/32; kb++) {
        const int k0 = kb * 32;
        __syncthreads();   // previous iter's Ks/Vs/Ps fully consumed

        // ---- load K,V tiles (32x64) as float4
        {
            const int dq = (t & 15) * 4;
            const int r  = t >> 4;      // 0..15
#pragma unroll
            for (int i = 0; i < 2; i++) {
                int rr = r + i*16;
                float4 kv = *reinterpret_cast<const float4*>(&Kg[(size_t)(k0 + rr)*DMODEL + dq]);
                float4 vv = *reinterpret_cast<const float4*>(&Vg[(size_t)(k0 + rr)*DMODEL + dq]);
                *reinterpret_cast<float4*>(&Ks[rr][dq]) = kv;
                *reinterpret_cast<float4*>(&Vs[rr][dq]) = vv;
            }
        }
        __syncthreads();

        // ---- scores: s[j] = Q[row,:] . K[quad*8+j,:]
        float s[8];
#pragma unroll
        for (int j = 0; j < 8; j++) s[j] = 0.f;

        const float4* q4 = reinterpret_cast<const float4*>(&Qs[row][0]);
#pragma unroll
        for (int d4 = 0; d4 < 16; d4++) {
            float4 qv = q4[d4];
#pragma unroll
            for (int j = 0; j < 8; j++) {
                float4 kv = reinterpret_cast<const float4*>(&Ks[quad*8 + j][0])[d4];
                s[j] += qv.x*kv.x + qv.y*kv.y + qv.z*kv.z + qv.w*kv.w;
            }
        }

        // ---- mask + scale
#pragma unroll
        for (int j = 0; j < 8; j++) {
            int mv = maskrow[k0 + quad*8 + j];
            s[j] = s[j]*inv + (float)mv * (-1e9f);
        }

        // ---- online softmax (row reduce over 4 lanes)
        float bm = s[0];
#pragma unroll
        for (int j = 1; j < 8; j++) bm = fmaxf(bm, s[j]);
        bm = fmaxf(bm, __shfl_xor_sync(0xffffffffu, bm, 1));
        bm = fmaxf(bm, __shfl_xor_sync(0xffffffffu, bm, 2));

        float mnew  = fmaxf(m, bm);
        float alpha = __expf(m - mnew);
        float ls = 0.f;
#pragma unroll
        for (int j = 0; j < 8; j++) {
            float p = __expf(s[j] - mnew);
            Ps[row][quad*8 + j] = p;
            ls += p;
        }
        ls += __shfl_xor_sync(0xffffffffu, ls, 1);
        ls += __shfl_xor_sync(0xffffffffu, ls, 2);
        l = l * alpha + ls;
        m = mnew;

#pragma unroll
        for (int u = 0; u < 4; u++) {
            acc[u].x *= alpha; acc[u].y *= alpha; acc[u].z *= alpha; acc[u].w *= alpha;
        }
        __syncwarp();  // Ps[row] written/read by lanes of the same warp

        // ---- O += P @ V   (owned cols: quad*16 .. quad*16+15)
#pragma unroll
        for (int kc = 0; kc < 32; kc++) {
            float pv = Ps[row][kc];
            const float4* v4 = reinterpret_cast<const float4*>(&Vs[kc][0]);
#pragma unroll
            for (int u = 0; u < 4; u++) {
                float4 vv = v4[quad*4 + u];
                acc[u].x += pv*vv.x; acc[u].y += pv*vv.y;
                acc[u].z += pv*vv.z; acc[u].w += pv*vv.w;
            }
        }
    }

    // ---- finalize + store ctx[b, q0+row, h*64 + quad*16 + ...]
    float invl = 1.f / l;
    float* ctxp = g_ctx + ((size_t)(b*SEQ + q0 + row))*DMODEL + h*HDIM + quad*16;
#pragma unroll
    for (int u = 0; u < 4; u++) {
        float4 o;
        o.x = acc[u].x * invl; o.y = acc[u].y * invl;
        o.z = acc[u].z * invl; o.w = acc[u].w * invl;
        *reinterpret_cast<float4*>(&ctxp[u*4]) = o;
    }
}

// ---------------------------------------------------------------------------
extern "C" void kernel_launch(void* const* d_in, const int* in_sizes, int n_in,
                              void* d_out, int out_size)
{
    const float* q    = (const float*)d_in[0];
    const float* k    = (const float*)d_in[1];
    const float* v    = (const float*)d_in[2];
    const int*   mask = (const int*)  d_in[3];
    const float* wq   = (const float*)d_in[4];
    const float* bq   = (const float*)d_in[5];
    const float* wk   = (const float*)d_in[6];
    const float* bk   = (const float*)d_in[7];
    const float* wv   = (const float*)d_in[8];
    const float* bv   = (const float*)d_in[9];
    const float* wo   = (const float*)d_in[10];
    const float* bo   = (const float*)d_in[11];
    float* out = (float*)d_out;

    dim3 gg(DMODEL/64, MTOT/64, 3);
    gemm_qkv_kernel<<<gg, 256>>>(q, k, v, wq, bq, wk, bk, wv, bv);

    dim3 ga(SEQ/64, BATCH*NHEAD);
    attn_kernel<<<ga, 256>>>(mask);

    dim3 go(DMODEL/64, MTOT/64, 1);
    gemm_o_kernel<<<go, 256>>>(wo, bo, out);
}

// round 2
// speedup vs baseline: 3.3428x; 3.3428x over previous
#include <cuda_runtime.h>
#include <cstdint>

#define NHEAD  16
#define DMODEL 1024
#define HDIM   64
#define BATCH  2
#define SEQ    2048
#define MTOT   (BATCH*SEQ)   // 4096

// Attention tiling
#define BQ 128
#define BK 64
#define QSTR 68
#define KSTR 68
#define PSTR 68
#define ATTN_SMEM_FLOATS (BQ*QSTR + 2*BK*KSTR + 2*BK*KSTR + BQ*PSTR)
#define ATTN_SMEM_BYTES  (ATTN_SMEM_FLOATS*4)

// Scratch (device globals: allocation-free per harness rules)
__device__ float g_qp[MTOT*DMODEL];
__device__ float g_kp[MTOT*DMODEL];
__device__ float g_vp[MTOT*DMODEL];
__device__ float g_ctx[MTOT*DMODEL];

// ---------------------------------------------------------------------------
// SGEMM body: C[M,N] = A[M,K] @ W[K,N] + bias    (M=4096, N=K=1024)
// ---------------------------------------------------------------------------
__device__ __forceinline__ void gemm_body(const float* __restrict__ A,
                                          const float* __restrict__ W,
                                          const float* __restrict__ bias,
                                          float* __restrict__ C)
{
    __shared__ float As[16][68];
    __shared__ float Ws[16][68];

    const int tid = threadIdx.x;
    const int tx = tid & 15;
    const int ty = tid >> 4;
    const int m0 = blockIdx.y * 64;
    const int n0 = blockIdx.x * 64;

    float acc[4][4];
#pragma unroll
    for (int i = 0; i < 4; i++)
#pragma unroll
        for (int j = 0; j < 4; j++) acc[i][j] = 0.f;

    const int lka = tid & 15;
    const int lma = tid >> 4;
    const int lnw = tid & 63;
    const int lkw = tid >> 6;

    for (int k0 = 0; k0 < DMODEL; k0 += 16) {
#pragma unroll
        for (int i = 0; i < 4; i++)
            As[lka][lma + i*16] = A[(size_t)(m0 + lma + i*16)*DMODEL + k0 + lka];
#pragma unroll
        for (int i = 0; i < 4; i++)
            Ws[lkw + i*4][lnw] = W[(size_t)(k0 + lkw + i*4)*DMODEL + n0 + lnw];
        __syncthreads();

#pragma unroll
        for (int kk = 0; kk < 16; kk++) {
            float4 a = *reinterpret_cast<const float4*>(&As[kk][ty*4]);
            float4 b = *reinterpret_cast<const float4*>(&Ws[kk][tx*4]);
            float av[4] = {a.x, a.y, a.z, a.w};
            float bv[4] = {b.x, b.y, b.z, b.w};
#pragma unroll
            for (int i = 0; i < 4; i++)
#pragma unroll
                for (int j = 0; j < 4; j++)
                    acc[i][j] += av[i] * bv[j];
        }
        __syncthreads();
    }

    float4 bb = *reinterpret_cast<const float4*>(&bias[n0 + tx*4]);
#pragma unroll
    for (int i = 0; i < 4; i++) {
        int m = m0 + ty*4 + i;
        float4 o;
        o.x = acc[i][0] + bb.x;
        o.y = acc[i][1] + bb.y;
        o.z = acc[i][2] + bb.z;
        o.w = acc[i][3] + bb.w;
        *reinterpret_cast<float4*>(&C[(size_t)m*DMODEL + n0 + tx*4]) = o;
    }
}

__global__ void gemm_qkv_kernel(const float* __restrict__ q,
                                const float* __restrict__ k,
                                const float* __restrict__ v,
                                const float* __restrict__ wq, const float* __restrict__ bq,
                                const float* __restrict__ wk, const float* __restrict__ bk,
                                const float* __restrict__ wv, const float* __restrict__ bv)
{
    const int which = blockIdx.z;
    const float* A    = (which == 0) ? q  : (which == 1) ? k  : v;
    const float* W    = (which == 0) ? wq : (which == 1) ? wk : wv;
    const float* bias = (which == 0) ? bq : (which == 1) ? bk : bv;
    float* C          = (which == 0) ? g_qp : (which == 1) ? g_kp : g_vp;
    gemm_body(A, W, bias, C);
}

__global__ void gemm_o_kernel(const float* __restrict__ wo,
                              const float* __restrict__ bo,
                              float* __restrict__ out)
{
    gemm_body(g_ctx, wo, bo, out);
}

// ---------------------------------------------------------------------------
// Flash attention, fp32, bank-conflict-free XOR-swizzled smem, cp.async
// double-buffered K/V. Tile: 128 q-rows x 64 k-rows, 256 threads.
// Thread t: rg=t>>3 (rows rg*4..+3), cg=t&7 (cols {cg*4..+3, 32+cg*4..+3}).
// ---------------------------------------------------------------------------
__device__ __forceinline__ uint32_t smem_u32(const void* p) {
    return (uint32_t)__cvta_generic_to_shared(p);
}

#define CPASYNC16(dst, src) \
    asm volatile("cp.async.cg.shared.global [%0], [%1], 16;" :: "r"(dst), "l"(src))
#define CP_COMMIT()  asm volatile("cp.async.commit_group;" ::: "memory")
#define CP_WAIT0()   asm volatile("cp.async.wait_group 0;" ::: "memory")

__device__ __forceinline__ void load_kv_tile(const float* __restrict__ Kg,
                                             const float* __restrict__ Vg,
                                             float* Ks, float* Vs,
                                             int k0, int buf,
                                             int lr, int lc, int lsw)
{
    const float* ksrc = Kg + (size_t)(k0 + lr)*DMODEL;
    const float* vsrc = Vg + (size_t)(k0 + lr)*DMODEL;
    float* kdst = Ks + buf*BK*KSTR + lr*KSTR;
    float* vdst = Vs + buf*BK*KSTR + lr*KSTR;
#pragma unroll
    for (int i = 0; i < 4; i++) {
        int ch = lc + i;
        int ph = ch ^ lsw;
        CPASYNC16(smem_u32(kdst + (ph << 2)), ksrc + (ch << 2));
        CPASYNC16(smem_u32(vdst + (ph << 2)), vsrc + (ch << 2));
    }
}

__global__ __launch_bounds__(256, 1) void attn_kernel(const int* __restrict__ mask)
{
    extern __shared__ float smn[];
    float* Qs = smn;                    // [BQ][QSTR]
    float* Ks = Qs + BQ*QSTR;           // [2][BK][KSTR]
    float* Vs = Ks + 2*BK*KSTR;         // [2][BK][KSTR]
    float* Ps = Vs + 2*BK*KSTR;         // [BQ][PSTR]

    const int t   = threadIdx.x;
    const int rg  = t >> 3;             // 0..31
    const int cg  = t & 7;              // 0..7
    const int r0  = rg << 2;
    const int rgl = rg & 7;             // (row>>2)&7 for this thread's rows
    const int b   = blockIdx.y >> 4;
    const int h   = blockIdx.y & 15;
    const int q0  = blockIdx.x * BQ;

    const float inv = 1.0f/(sqrtf(64.0f) + 1e-8f);

    const float* Qg = g_qp + ((size_t)(b*SEQ + q0))*DMODEL + h*HDIM;
    const float* Kg = g_kp + ((size_t)(b*SEQ))*DMODEL + h*HDIM;
    const float* Vg = g_vp + ((size_t)(b*SEQ))*DMODEL + h*HDIM;

    // K/V loader mapping
    const int lr  = t >> 2;             // row 0..63
    const int lc  = (t & 3) << 2;       // chunk base {0,4,8,12}
    const int lsw = (lr >> 2) & 7;

    // prologue: start K/V tile 0
    load_kv_tile(Kg, Vg, Ks, Vs, 0, 0, lr, lc, lsw);
    CP_COMMIT();

    // load Q tile (swizzled)
    {
        int qr  = t >> 1;
        int qh  = (t & 1) << 3;
        int qsw = (qr >> 2) & 7;
        const float* qsrc = Qg + (size_t)qr*DMODEL;
        float* qdst = Qs + qr*QSTR;
#pragma unroll
        for (int i = 0; i < 8; i++) {
            int ch = qh + i, ph = ch ^ qsw;
            *reinterpret_cast<float4*>(qdst + (ph << 2)) =
                *reinterpret_cast<const float4*>(qsrc + (ch << 2));
        }
    }

    float m_[4], l_[4];
    float4 a0[4], a1[4];
#pragma unroll
    for (int i = 0; i < 4; i++) {
        m_[i] = -1e30f; l_[i] = 0.f;
        a0[i] = make_float4(0.f,0.f,0.f,0.f);
        a1[i] = make_float4(0.f,0.f,0.f,0.f);
    }

    for (int kb = 0; kb < SEQ/BK; kb++) {
        const int cur = kb & 1;
        CP_WAIT0();
        __syncthreads();
        if (kb + 1 < SEQ/BK) {
            load_kv_tile(Kg, Vg, Ks, Vs, (kb+1)*BK, cur ^ 1, lr, lc, lsw);
            CP_COMMIT();
        }
        const float* Kb = Ks + cur*BK*KSTR;
        const float* Vb = Vs + cur*BK*KSTR;

        // ---- scores: s[i][j] = Q[r0+i,:] . K[C(j),:]
        float s[4][8];
#pragma unroll
        for (int i = 0; i < 4; i++)
#pragma unroll
            for (int j = 0; j < 8; j++) s[i][j] = 0.f;

#pragma unroll 4
        for (int d4 = 0; d4 < 16; d4++) {
            float4 qv[4];
#pragma unroll
            for (int i = 0; i < 4; i++)
                qv[i] = *reinterpret_cast<const float4*>(
                    &Qs[(r0+i)*QSTR + ((d4 ^ rgl) << 2)]);
#pragma unroll
            for (int j = 0; j < 8; j++) {
                int kr = (cg << 2) + (j & 3) + ((j >> 2) << 5);
                float4 kv = *reinterpret_cast<const float4*>(
                    &Kb[kr*KSTR + ((d4 ^ cg) << 2)]);
#pragma unroll
                for (int i = 0; i < 4; i++) {
                    s[i][j] += qv[i].x*kv.x + qv[i].y*kv.y
                             + qv[i].z*kv.z + qv[i].w*kv.w;
                }
            }
        }

        // ---- mask + scale + online softmax + write P
        const int k0 = kb*BK;
#pragma unroll
        for (int i = 0; i < 4; i++) {
            const int* mrow = mask + ((size_t)b*SEQ + (q0+r0+i))*SEQ + k0 + (cg << 2);
            int4 mv0 = *reinterpret_cast<const int4*>(mrow);
            int4 mv1 = *reinterpret_cast<const int4*>(mrow + 32);
            s[i][0] = s[i][0]*inv - 1e9f*(float)mv0.x;
            s[i][1] = s[i][1]*inv - 1e9f*(float)mv0.y;
            s[i][2] = s[i][2]*inv - 1e9f*(float)mv0.z;
            s[i][3] = s[i][3]*inv - 1e9f*(float)mv0.w;
            s[i][4] = s[i][4]*inv - 1e9f*(float)mv1.x;
            s[i][5] = s[i][5]*inv - 1e9f*(float)mv1.y;
            s[i][6] = s[i][6]*inv - 1e9f*(float)mv1.z;
            s[i][7] = s[i][7]*inv - 1e9f*(float)mv1.w;

            float bm = s[i][0];
#pragma unroll
            for (int j = 1; j < 8; j++) bm = fmaxf(bm, s[i][j]);
            bm = fmaxf(bm, __shfl_xor_sync(0xffffffffu, bm, 1));
            bm = fmaxf(bm, __shfl_xor_sync(0xffffffffu, bm, 2));
            bm = fmaxf(bm, __shfl_xor_sync(0xffffffffu, bm, 4));

            float mn = fmaxf(m_[i], bm);
            float al = __expf(m_[i] - mn);
            m_[i] = mn;

            float p[8];
            float ls = 0.f;
#pragma unroll
            for (int j = 0; j < 8; j++) { p[j] = __expf(s[i][j] - mn); ls += p[j]; }
            ls += __shfl_xor_sync(0xffffffffu, ls, 1);
            ls += __shfl_xor_sync(0xffffffffu, ls, 2);
            ls += __shfl_xor_sync(0xffffffffu, ls, 4);
            l_[i] = l_[i]*al + ls;

            a0[i].x *= al; a0[i].y *= al; a0[i].z *= al; a0[i].w *= al;
            a1[i].x *= al; a1[i].y *= al; a1[i].z *= al; a1[i].w *= al;

            float4 P0 = make_float4(p[0], p[1], p[2], p[3]);
            float4 P1 = make_float4(p[4], p[5], p[6], p[7]);
            *reinterpret_cast<float4*>(&Ps[(r0+i)*PSTR + ((cg       ^ rgl) << 2)]) = P0;
            *reinterpret_cast<float4*>(&Ps[(r0+i)*PSTR + (((cg + 8) ^ rgl) << 2)]) = P1;
        }
        __syncwarp();

        // ---- O += P @ V
#pragma unroll 4
        for (int k4 = 0; k4 < 16; k4++) {
            float4 pv[4];
#pragma unroll
            for (int i = 0; i < 4; i++)
                pv[i] = *reinterpret_cast<const float4*>(
                    &Ps[(r0+i)*PSTR + ((k4 ^ rgl) << 2)]);
            const int vx = k4 & 7;
#pragma unroll
            for (int u = 0; u < 4; u++) {
                int kc = (k4 << 2) + u;
                float4 v0 = *reinterpret_cast<const float4*>(
                    &Vb[kc*KSTR + ((cg ^ vx) << 2)]);
                float4 v1 = *reinterpret_cast<const float4*>(
                    &Vb[kc*KSTR + (((cg + 8) ^ vx) << 2)]);
#pragma unroll
                for (int i = 0; i < 4; i++) {
                    float pp = reinterpret_cast<const float*>(&pv[i])[u];
                    a0[i].x += pp*v0.x; a0[i].y += pp*v0.y;
                    a0[i].z += pp*v0.z; a0[i].w += pp*v0.w;
                    a1[i].x += pp*v1.x; a1[i].y += pp*v1.y;
                    a1[i].z += pp*v1.z; a1[i].w += pp*v1.w;
                }
            }
        }
    }

    // ---- finalize
#pragma unroll
    for (int i = 0; i < 4; i++) {
        float ivl = 1.f / l_[i];
        float* op = g_ctx + ((size_t)(b*SEQ + q0 + r0 + i))*DMODEL + h*HDIM;
        float4 o0, o1;
        o0.x = a0[i].x*ivl; o0.y = a0[i].y*ivl; o0.z = a0[i].z*ivl; o0.w = a0[i].w*ivl;
        o1.x = a1[i].x*ivl; o1.y = a1[i].y*ivl; o1.z = a1[i].z*ivl; o1.w = a1[i].w*ivl;
        *reinterpret_cast<float4*>(op + (cg << 2))      = o0;
        *reinterpret_cast<float4*>(op + 32 + (cg << 2)) = o1;
    }
}

// ---------------------------------------------------------------------------
extern "C" void kernel_launch(void* const* d_in, const int* in_sizes, int n_in,
                              void* d_out, int out_size)
{
    const float* q    = (const float*)d_in[0];
    const float* k    = (const float*)d_in[1];
    const float* v    = (const float*)d_in[2];
    const int*   mask = (const int*)  d_in[3];
    const float* wq   = (const float*)d_in[4];
    const float* bq   = (const float*)d_in[5];
    const float* wk   = (const float*)d_in[6];
    const float* bk   = (const float*)d_in[7];
    const float* wv   = (const float*)d_in[8];
    const float* bv   = (const float*)d_in[9];
    const float* wo   = (const float*)d_in[10];
    const float* bo   = (const float*)d_in[11];
    float* out = (float*)d_out;

    cudaFuncSetAttribute(attn_kernel,
                         cudaFuncAttributeMaxDynamicSharedMemorySize,
                         ATTN_SMEM_BYTES);

    dim3 gg(DMODEL/64, MTOT/64, 3);
    gemm_qkv_kernel<<<gg, 256>>>(q, k, v, wq, bq, wk, bk, wv, bv);

    dim3 ga(SEQ/BQ, BATCH*NHEAD);
    attn_kernel<<<ga, 256, ATTN_SMEM_BYTES>>>(mask);

    dim3 go(DMODEL/64, MTOT/64, 1);
    gemm_o_kernel<<<go, 256>>>(wo, bo, out);
}

// round 3
// speedup vs baseline: 3.4331x; 1.0270x over previous
#include <cuda_runtime.h>
#include <cstdint>

#define NHEAD  16
#define DMODEL 1024
#define HDIM   64
#define BATCH  2
#define SEQ    2048
#define MTOT   (BATCH*SEQ)   // 4096

// Attention tiling
#define BQ 128
#define BK 64
#define QSTR 68
#define KSTR 68
#define PSTR 68
#define ATTN_SMEM_FLOATS (BQ*QSTR + 2*BK*KSTR + 2*BK*KSTR + BQ*PSTR)
#define ATTN_SMEM_BYTES  (ATTN_SMEM_FLOATS*4)

// Scratch (device globals: allocation-free per harness rules)
__device__ float g_qp[MTOT*DMODEL];
__device__ float g_kp[MTOT*DMODEL];
__device__ float g_vp[MTOT*DMODEL];
__device__ float g_ctx[MTOT*DMODEL];

// ---------------------------------------------------------------------------
// f32x2 packed-math helpers (FFMA2: 2 FMAs per instruction, sm_100+)
// ---------------------------------------------------------------------------
typedef unsigned long long u64t;

union F4Q { float4 f; u64t q[2]; };

__device__ __forceinline__ void ffma2(u64t& d, u64t a, u64t b) {
    asm("fma.rn.f32x2 %0, %1, %2, %0;" : "+l"(d) : "l"(a), "l"(b));
}
__device__ __forceinline__ void fmul2(u64t& d, u64t a) {
    asm("mul.rn.f32x2 %0, %0, %1;" : "+l"(d) : "l"(a));
}
__device__ __forceinline__ u64t bcast2(float x) {
    u64t r; unsigned xi = __float_as_uint(x);
    asm("mov.b64 %0, {%1, %1};" : "=l"(r) : "r"(xi));
    return r;
}
__device__ __forceinline__ void unpack2(u64t q, float& lo, float& hi) {
    unsigned a, b;
    asm("mov.b64 {%0, %1}, %2;" : "=r"(a), "=r"(b) : "l"(q));
    lo = __uint_as_float(a); hi = __uint_as_float(b);
}
__device__ __forceinline__ float hadd2(u64t q) {
    float lo, hi; unpack2(q, lo, hi); return lo + hi;
}

// ---------------------------------------------------------------------------
// SGEMM body: C[M,N] = A[M,K] @ W[K,N] + bias    (M=4096, N=K=1024)
// 64x64 tile, BK=16, 256 threads, 4x4 per thread, FFMA2 paired along m.
// ---------------------------------------------------------------------------
__device__ __forceinline__ void gemm_body(const float* __restrict__ A,
                                          const float* __restrict__ W,
                                          const float* __restrict__ bias,
                                          float* __restrict__ C)
{
    __shared__ float As[16][68];   // As[k][m]
    __shared__ float Ws[16][68];   // Ws[k][n]

    const int tid = threadIdx.x;
    const int tx = tid & 15;
    const int ty = tid >> 4;
    const int m0 = blockIdx.y * 64;
    const int n0 = blockIdx.x * 64;

    u64t acc2[2][4];   // [m-pair][n], lanes = (row 2ip, row 2ip+1)
#pragma unroll
    for (int i = 0; i < 2; i++)
#pragma unroll
        for (int j = 0; j < 4; j++) acc2[i][j] = 0ull;

    const int lka = tid & 15;
    const int lma = tid >> 4;
    const int lnw = tid & 63;
    const int lkw = tid >> 6;

    for (int k0 = 0; k0 < DMODEL; k0 += 16) {
#pragma unroll
        for (int i = 0; i < 4; i++)
            As[lka][lma + i*16] = A[(size_t)(m0 + lma + i*16)*DMODEL + k0 + lka];
#pragma unroll
        for (int i = 0; i < 4; i++)
            Ws[lkw + i*4][lnw] = W[(size_t)(k0 + lkw + i*4)*DMODEL + n0 + lnw];
        __syncthreads();

#pragma unroll
        for (int kk = 0; kk < 16; kk++) {
            F4Q a; a.f = *reinterpret_cast<const float4*>(&As[kk][ty*4]);
            float4 b = *reinterpret_cast<const float4*>(&Ws[kk][tx*4]);
            u64t b2[4];
            b2[0] = bcast2(b.x); b2[1] = bcast2(b.y);
            b2[2] = bcast2(b.z); b2[3] = bcast2(b.w);
#pragma unroll
            for (int j = 0; j < 4; j++) {
                ffma2(acc2[0][j], a.q[0], b2[j]);
                ffma2(acc2[1][j], a.q[1], b2[j]);
            }
        }
        __syncthreads();
    }

    float4 bb = *reinterpret_cast<const float4*>(&bias[n0 + tx*4]);
    float bias4[4] = {bb.x, bb.y, bb.z, bb.w};
#pragma unroll
    for (int ip = 0; ip < 2; ip++) {
        float r0[4], r1[4];
#pragma unroll
        for (int j = 0; j < 4; j++) unpack2(acc2[ip][j], r0[j], r1[j]);
        int mA = m0 + ty*4 + 2*ip;
        float4 oA, oB;
        oA.x = r0[0]+bias4[0]; oA.y = r0[1]+bias4[1]; oA.z = r0[2]+bias4[2]; oA.w = r0[3]+bias4[3];
        oB.x = r1[0]+bias4[0]; oB.y = r1[1]+bias4[1]; oB.z = r1[2]+bias4[2]; oB.w = r1[3]+bias4[3];
        *reinterpret_cast<float4*>(&C[(size_t)mA*DMODEL + n0 + tx*4]) = oA;
        *reinterpret_cast<float4*>(&C[(size_t)(mA+1)*DMODEL + n0 + tx*4]) = oB;
    }
}

__global__ void gemm_qkv_kernel(const float* __restrict__ q,
                                const float* __restrict__ k,
                                const float* __restrict__ v,
                                const float* __restrict__ wq, const float* __restrict__ bq,
                                const float* __restrict__ wk, const float* __restrict__ bk,
                                const float* __restrict__ wv, const float* __restrict__ bv)
{
    const int which = blockIdx.z;
    const float* A    = (which == 0) ? q  : (which == 1) ? k  : v;
    const float* W    = (which == 0) ? wq : (which == 1) ? wk : wv;
    const float* bias = (which == 0) ? bq : (which == 1) ? bk : bv;
    float* C          = (which == 0) ? g_qp : (which == 1) ? g_kp : g_vp;
    gemm_body(A, W, bias, C);
}

__global__ void gemm_o_kernel(const float* __restrict__ wo,
                              const float* __restrict__ bo,
                              float* __restrict__ out)
{
    gemm_body(g_ctx, wo, bo, out);
}

// ---------------------------------------------------------------------------
// Flash attention, fp32, swizzled smem, cp.async double-buffer, FFMA2 math.
// Tile: 128 q-rows x 64 k-rows, 256 threads.
// Thread t: rg=t>>3 (rows rg*4..+3), cg=t&7 (cols {cg*4..+3, 32+cg*4..+3}).
// ---------------------------------------------------------------------------
__device__ __forceinline__ uint32_t smem_u32(const void* p) {
    return (uint32_t)__cvta_generic_to_shared(p);
}

#define CPASYNC16(dst, src) \
    asm volatile("cp.async.cg.shared.global [%0], [%1], 16;" :: "r"(dst), "l"(src))
#define CP_COMMIT()  asm volatile("cp.async.commit_group;" ::: "memory")
#define CP_WAIT0()   asm volatile("cp.async.wait_group 0;" ::: "memory")

__device__ __forceinline__ void load_kv_tile(const float* __restrict__ Kg,
                                             const float* __restrict__ Vg,
                                             float* Ks, float* Vs,
                                             int k0, int buf,
                                             int lr, int lc, int lsw)
{
    const float* ksrc = Kg + (size_t)(k0 + lr)*DMODEL;
    const float* vsrc = Vg + (size_t)(k0 + lr)*DMODEL;
    float* kdst = Ks + buf*BK*KSTR + lr*KSTR;
    float* vdst = Vs + buf*BK*KSTR + lr*KSTR;
#pragma unroll
    for (int i = 0; i < 4; i++) {
        int ch = lc + i;
        int ph = ch ^ lsw;
        CPASYNC16(smem_u32(kdst + (ph << 2)), ksrc + (ch << 2));
        CPASYNC16(smem_u32(vdst + (ph << 2)), vsrc + (ch << 2));
    }
}

__global__ __launch_bounds__(256, 1) void attn_kernel(const int* __restrict__ mask)
{
    extern __shared__ float smn[];
    float* Qs = smn;                    // [BQ][QSTR]
    float* Ks = Qs + BQ*QSTR;           // [2][BK][KSTR]
    float* Vs = Ks + 2*BK*KSTR;         // [2][BK][KSTR]
    float* Ps = Vs + 2*BK*KSTR;         // [BQ][PSTR]

    const int t   = threadIdx.x;
    const int rg  = t >> 3;             // 0..31
    const int cg  = t & 7;              // 0..7
    const int r0  = rg << 2;
    const int rgl = rg & 7;
    const int b   = blockIdx.y >> 4;
    const int h   = blockIdx.y & 15;
    const int q0  = blockIdx.x * BQ;

    const float inv = 1.0f/(sqrtf(64.0f) + 1e-8f);

    const float* Qg = g_qp + ((size_t)(b*SEQ + q0))*DMODEL + h*HDIM;
    const float* Kg = g_kp + ((size_t)(b*SEQ))*DMODEL + h*HDIM;
    const float* Vg = g_vp + ((size_t)(b*SEQ))*DMODEL + h*HDIM;

    const int lr  = t >> 2;
    const int lc  = (t & 3) << 2;
    const int lsw = (lr >> 2) & 7;

    load_kv_tile(Kg, Vg, Ks, Vs, 0, 0, lr, lc, lsw);
    CP_COMMIT();

    // load Q tile (swizzled)
    {
        int qr  = t >> 1;
        int qh  = (t & 1) << 3;
        int qsw = (qr >> 2) & 7;
        const float* qsrc = Qg + (size_t)qr*DMODEL;
        float* qdst = Qs + qr*QSTR;
#pragma unroll
        for (int i = 0; i < 8; i++) {
            int ch = qh + i, ph = ch ^ qsw;
            *reinterpret_cast<float4*>(qdst + (ph << 2)) =
                *reinterpret_cast<const float4*>(qsrc + (ch << 2));
        }
    }

    float m_[4], l_[4];
    u64t aq[4][4];   // O accumulator: [row i][qword: c01,c23,c45(+32),c67(+32)]
#pragma unroll
    for (int i = 0; i < 4; i++) {
        m_[i] = -1e30f; l_[i] = 0.f;
#pragma unroll
        for (int w = 0; w < 4; w++) aq[i][w] = 0ull;
    }

    for (int kb = 0; kb < SEQ/BK; kb++) {
        const int cur = kb & 1;
        CP_WAIT0();
        __syncthreads();
        if (kb + 1 < SEQ/BK) {
            load_kv_tile(Kg, Vg, Ks, Vs, (kb+1)*BK, cur ^ 1, lr, lc, lsw);
            CP_COMMIT();
        }
        const float* Kb = Ks + cur*BK*KSTR;
        const float* Vb = Vs + cur*BK*KSTR;

        // ---- scores via FFMA2: two partial sums per score, zero packs
        u64t s2[4][8];
#pragma unroll
        for (int i = 0; i < 4; i++)
#pragma unroll
            for (int j = 0; j < 8; j++) s2[i][j] = 0ull;

#pragma unroll 4
        for (int d4 = 0; d4 < 16; d4++) {
            F4Q qv[4];
#pragma unroll
            for (int i = 0; i < 4; i++)
                qv[i].f = *reinterpret_cast<const float4*>(
                    &Qs[(r0+i)*QSTR + ((d4 ^ rgl) << 2)]);
#pragma unroll
            for (int j = 0; j < 8; j++) {
                int kr = (cg << 2) + (j & 3) + ((j >> 2) << 5);
                F4Q kv;
                kv.f = *reinterpret_cast<const float4*>(
                    &Kb[kr*KSTR + ((d4 ^ cg) << 2)]);
#pragma unroll
                for (int i = 0; i < 4; i++) {
                    ffma2(s2[i][j], qv[i].q[0], kv.q[0]);
                    ffma2(s2[i][j], qv[i].q[1], kv.q[1]);
                }
            }
        }

        // ---- mask + scale + online softmax + write P
        const int k0 = kb*BK;
#pragma unroll
        for (int i = 0; i < 4; i++) {
            float s[8];
#pragma unroll
            for (int j = 0; j < 8; j++) s[j] = hadd2(s2[i][j]);

            const int* mrow = mask + ((size_t)b*SEQ + (q0+r0+i))*SEQ + k0 + (cg << 2);
            int4 mv0 = *reinterpret_cast<const int4*>(mrow);
            int4 mv1 = *reinterpret_cast<const int4*>(mrow + 32);
            s[0] = s[0]*inv - 1e9f*(float)mv0.x;
            s[1] = s[1]*inv - 1e9f*(float)mv0.y;
            s[2] = s[2]*inv - 1e9f*(float)mv0.z;
            s[3] = s[3]*inv - 1e9f*(float)mv0.w;
            s[4] = s[4]*inv - 1e9f*(float)mv1.x;
            s[5] = s[5]*inv - 1e9f*(float)mv1.y;
            s[6] = s[6]*inv - 1e9f*(float)mv1.z;
            s[7] = s[7]*inv - 1e9f*(float)mv1.w;

            float bm = s[0];
#pragma unroll
            for (int j = 1; j < 8; j++) bm = fmaxf(bm, s[j]);
            bm = fmaxf(bm, __shfl_xor_sync(0xffffffffu, bm, 1));
            bm = fmaxf(bm, __shfl_xor_sync(0xffffffffu, bm, 2));
            bm = fmaxf(bm, __shfl_xor_sync(0xffffffffu, bm, 4));

            float mn = fmaxf(m_[i], bm);
            float al = __expf(m_[i] - mn);
            m_[i] = mn;

            float p[8];
            float ls = 0.f;
#pragma unroll
            for (int j = 0; j < 8; j++) { p[j] = __expf(s[j] - mn); ls += p[j]; }
            ls += __shfl_xor_sync(0xffffffffu, ls, 1);
            ls += __shfl_xor_sync(0xffffffffu, ls, 2);
            ls += __shfl_xor_sync(0xffffffffu, ls, 4);
            l_[i] = l_[i]*al + ls;

            u64t al2 = bcast2(al);
#pragma unroll
            for (int w = 0; w < 4; w++) fmul2(aq[i][w], al2);

            float4 P0 = make_float4(p[0], p[1], p[2], p[3]);
            float4 P1 = make_float4(p[4], p[5], p[6], p[7]);
            *reinterpret_cast<float4*>(&Ps[(r0+i)*PSTR + ((cg       ^ rgl) << 2)]) = P0;
            *reinterpret_cast<float4*>(&Ps[(r0+i)*PSTR + (((cg + 8) ^ rgl) << 2)]) = P1;
        }
        __syncwarp();

        // ---- O += P @ V  via FFMA2 (columns paired)
#pragma unroll 4
        for (int k4 = 0; k4 < 16; k4++) {
            F4Q pv[4];
#pragma unroll
            for (int i = 0; i < 4; i++)
                pv[i].f = *reinterpret_cast<const float4*>(
                    &Ps[(r0+i)*PSTR + ((k4 ^ rgl) << 2)]);
            const int vx = k4 & 7;
#pragma unroll
            for (int u = 0; u < 4; u++) {
                int kc = (k4 << 2) + u;
                F4Q v0, v1;
                v0.f = *reinterpret_cast<const float4*>(
                    &Vb[kc*KSTR + ((cg ^ vx) << 2)]);
                v1.f = *reinterpret_cast<const float4*>(
                    &Vb[kc*KSTR + (((cg + 8) ^ vx) << 2)]);
#pragma unroll
                for (int i = 0; i < 4; i++) {
                    float pp = reinterpret_cast<const float*>(&pv[i].f)[u];
                    u64t pp2 = bcast2(pp);
                    ffma2(aq[i][0], pp2, v0.q[0]);
                    ffma2(aq[i][1], pp2, v0.q[1]);
                    ffma2(aq[i][2], pp2, v1.q[0]);
                    ffma2(aq[i][3], pp2, v1.q[1]);
                }
            }
        }
    }

    // ---- finalize
#pragma unroll
    for (int i = 0; i < 4; i++) {
        float ivl = 1.f / l_[i];
        float* op = g_ctx + ((size_t)(b*SEQ + q0 + r0 + i))*DMODEL + h*HDIM;
        float c[8];
        unpack2(aq[i][0], c[0], c[1]);
        unpack2(aq[i][1], c[2], c[3]);
        unpack2(aq[i][2], c[4], c[5]);
        unpack2(aq[i][3], c[6], c[7]);
        float4 o0, o1;
        o0.x = c[0]*ivl; o0.y = c[1]*ivl; o0.z = c[2]*ivl; o0.w = c[3]*ivl;
        o1.x = c[4]*ivl; o1.y = c[5]*ivl; o1.z = c[6]*ivl; o1.w = c[7]*ivl;
        *reinterpret_cast<float4*>(op + (cg << 2))      = o0;
        *reinterpret_cast<float4*>(op + 32 + (cg << 2)) = o1;
    }
}

// ---------------------------------------------------------------------------
extern "C" void kernel_launch(void* const* d_in, const int* in_sizes, int n_in,
                              void* d_out, int out_size)
{
    const float* q    = (const float*)d_in[0];
    const float* k    = (const float*)d_in[1];
    const float* v    = (const float*)d_in[2];
    const int*   mask = (const int*)  d_in[3];
    const float* wq   = (const float*)d_in[4];
    const float* bq   = (const float*)d_in[5];
    const float* wk   = (const float*)d_in[6];
    const float* bk   = (const float*)d_in[7];
    const float* wv   = (const float*)d_in[8];
    const float* bv   = (const float*)d_in[9];
    const float* wo   = (const float*)d_in[10];
    const float* bo   = (const float*)d_in[11];
    float* out = (float*)d_out;

    cudaFuncSetAttribute(attn_kernel,
                         cudaFuncAttributeMaxDynamicSharedMemorySize,
                         ATTN_SMEM_BYTES);

    dim3 gg(DMODEL/64, MTOT/64, 3);
    gemm_qkv_kernel<<<gg, 256>>>(q, k, v, wq, bq, wk, bk, wv, bv);

    dim3 ga(SEQ/BQ, BATCH*NHEAD);
    attn_kernel<<<ga, 256, ATTN_SMEM_BYTES>>>(mask);

    dim3 go(DMODEL/64, MTOT/64, 1);
    gemm_o_kernel<<<go, 256>>>(wo, bo, out);
}

// round 5
// speedup vs baseline: 8.5177x; 2.4811x over previous
#include <cuda_runtime.h>
#include <cuda_bf16.h>
#include <cstdint>

#define NHEAD  16
#define DMODEL 1024
#define HDIM   64
#define BATCH  2
#define SEQ    2048
#define MTOT   (BATCH*SEQ)   // 4096
#define MWORDS (SEQ/32)      // 64 mask words per row

// ---------------- device global scratch (allocation-free) ----------------
__device__ __nv_bfloat16 g_q_hi[MTOT*DMODEL],  g_q_lo[MTOT*DMODEL];
__device__ __nv_bfloat16 g_k_hi[MTOT*DMODEL],  g_k_lo[MTOT*DMODEL];
__device__ __nv_bfloat16 g_v_hi[MTOT*DMODEL],  g_v_lo[MTOT*DMODEL];
__device__ __nv_bfloat16 g_wt_hi[4*DMODEL*DMODEL], g_wt_lo[4*DMODEL*DMODEL];
__device__ __nv_bfloat16 g_qp_hi[MTOT*DMODEL], g_qp_lo[MTOT*DMODEL];
__device__ __nv_bfloat16 g_kp_hi[MTOT*DMODEL], g_kp_lo[MTOT*DMODEL];
__device__ __nv_bfloat16 g_vp_hi[MTOT*DMODEL], g_vp_lo[MTOT*DMODEL];
__device__ __nv_bfloat16 g_ctx_hi[MTOT*DMODEL], g_ctx_lo[MTOT*DMODEL];
__device__ uint32_t g_maskbits[BATCH*SEQ*MWORDS];

// ---------------- helpers ----------------
__device__ __forceinline__ uint32_t smem_u32(const void* p) {
    return (uint32_t)__cvta_generic_to_shared(p);
}
__device__ __forceinline__ uint32_t pack_bf16x2(float lo, float hi) {
    uint32_t d;
    asm("cvt.rn.bf16x2.f32 %0, %1, %2;" : "=r"(d) : "f"(hi), "f"(lo));
    return d;
}
__device__ __forceinline__ float bf16lo_f(uint32_t u){ return __uint_as_float(u << 16); }
__device__ __forceinline__ float bf16hi_f(uint32_t u){ return __uint_as_float(u & 0xffff0000u); }

__device__ __forceinline__ void mma16816(float* d, const uint32_t* a, const uint32_t* b) {
    asm volatile("mma.sync.aligned.m16n8k16.row.col.f32.bf16.bf16.f32 "
        "{%0,%1,%2,%3}, {%4,%5,%6,%7}, {%8,%9}, {%0,%1,%2,%3};"
        : "+f"(d[0]), "+f"(d[1]), "+f"(d[2]), "+f"(d[3])
        : "r"(a[0]), "r"(a[1]), "r"(a[2]), "r"(a[3]), "r"(b[0]), "r"(b[1]));
}
__device__ __forceinline__ void ldm_x4(uint32_t* r, uint32_t addr) {
    asm volatile("ldmatrix.sync.aligned.m8n8.x4.shared.b16 {%0,%1,%2,%3}, [%4];"
        : "=r"(r[0]), "=r"(r[1]), "=r"(r[2]), "=r"(r[3]) : "r"(addr));
}
__device__ __forceinline__ void ldm_x2(uint32_t* r, uint32_t addr) {
    asm volatile("ldmatrix.sync.aligned.m8n8.x2.shared.b16 {%0,%1}, [%2];"
        : "=r"(r[0]), "=r"(r[1]) : "r"(addr));
}
__device__ __forceinline__ void ldm_x2t(uint32_t* r, uint32_t addr) {
    asm volatile("ldmatrix.sync.aligned.m8n8.x2.trans.shared.b16 {%0,%1}, [%2];"
        : "=r"(r[0]), "=r"(r[1]) : "r"(addr));
}
#define CPASYNC16(dst, src) \
    asm volatile("cp.async.cg.shared.global [%0], [%1], 16;" :: "r"(dst), "l"(src))
#define CP_COMMIT()   asm volatile("cp.async.commit_group;" ::: "memory")
#define CP_WAIT(n)    asm volatile("cp.async.wait_group %0;" :: "n"(n) : "memory")

// tile with 64 bf16 cols = 128B rows; chunk = 16B unit, XOR swizzle
__device__ __forceinline__ int phys(int row, int chunk) {
    return row*128 + ((chunk ^ (row & 7)) << 4);
}

// ---------------- prep kernels ----------------
__global__ void cvt_inputs_kernel(const float* __restrict__ q,
                                  const float* __restrict__ k,
                                  const float* __restrict__ v)
{
    const int z = blockIdx.y;
    const float* src = (z == 0) ? q : (z == 1) ? k : v;
    __nv_bfloat16* dh = (z == 0) ? g_q_hi : (z == 1) ? g_k_hi : g_v_hi;
    __nv_bfloat16* dl = (z == 0) ? g_q_lo : (z == 1) ? g_k_lo : g_v_lo;
    size_t i = (size_t)blockIdx.x*256 + threadIdx.x;   // 1 float4 each
    float4 x = reinterpret_cast<const float4*>(src)[i];
    uint32_t h0 = pack_bf16x2(x.x, x.y);
    uint32_t h1 = pack_bf16x2(x.z, x.w);
    uint32_t l0 = pack_bf16x2(x.x - bf16lo_f(h0), x.y - bf16hi_f(h0));
    uint32_t l1 = pack_bf16x2(x.z - bf16lo_f(h1), x.w - bf16hi_f(h1));
    reinterpret_cast<uint2*>(dh)[i] = make_uint2(h0, h1);
    reinterpret_cast<uint2*>(dl)[i] = make_uint2(l0, l1);
}

__global__ void cvt_w_kernel(const float* __restrict__ wq,
                             const float* __restrict__ wk,
                             const float* __restrict__ wv,
                             const float* __restrict__ wo)
{
    __shared__ float ts[32][33];
    const int wsel = blockIdx.z;
    const float* W = (wsel == 0) ? wq : (wsel == 1) ? wk : (wsel == 2) ? wv : wo;
    const int k0 = blockIdx.x*32, n0 = blockIdx.y*32;
    const int tx = threadIdx.x, ty = threadIdx.y;
#pragma unroll
    for (int i = 0; i < 4; i++)
        ts[ty + 8*i][tx] = W[(size_t)(k0 + ty + 8*i)*DMODEL + n0 + tx];
    __syncthreads();
    __nv_bfloat16* dh = g_wt_hi + (size_t)wsel*DMODEL*DMODEL;
    __nv_bfloat16* dl = g_wt_lo + (size_t)wsel*DMODEL*DMODEL;
#pragma unroll
    for (int i = 0; i < 4; i++) {
        float x = ts[tx][ty + 8*i];
        __nv_bfloat16 h = __float2bfloat16(x);
        float r = x - __bfloat162float(h);
        size_t o = (size_t)(n0 + ty + 8*i)*DMODEL + k0 + tx;
        dh[o] = h;
        dl[o] = __float2bfloat16(r);
    }
}

__global__ void maskbits_kernel(const int* __restrict__ mask)
{
    size_t i = (size_t)blockIdx.x*256 + threadIdx.x;
    int v = mask[i];
    uint32_t bits = __ballot_sync(0xffffffffu, v != 0);
    if ((threadIdx.x & 31) == 0) g_maskbits[i >> 5] = bits;
}

// ---------------- GEMM via mma.sync (bf16 hi/lo split) ----------------
// C[M,N] = A[M,K] @ W[K,N] + bias.  CTA 128x128, 8 warps (32x64 each), KC=64.
#define GT_SZ  16384
#define GBUF   (4*GT_SZ)
#define GSMEM  (2*GBUF)   // 131072

__device__ __forceinline__ void gemm_issue(uint32_t smb, int buf, int c,
                                           const __nv_bfloat16* a_hi,
                                           const __nv_bfloat16* a_lo,
                                           const __nv_bfloat16* b_hi,
                                           const __nv_bfloat16* b_lo,
                                           int m0, int n0, int t)
{
    const int lr  = t >> 1;
    const int lc0 = (t & 1) * 4;
    const int k0  = c * 64;
    const __nv_bfloat16* sa_h = a_hi + (size_t)(m0 + lr)*DMODEL + k0;
    const __nv_bfloat16* sa_l = a_lo + (size_t)(m0 + lr)*DMODEL + k0;
    const __nv_bfloat16* sb_h = b_hi + (size_t)(n0 + lr)*DMODEL + k0;
    const __nv_bfloat16* sb_l = b_lo + (size_t)(n0 + lr)*DMODEL + k0;
    uint32_t base = smb + buf*GBUF;
#pragma unroll
    for (int i = 0; i < 4; i++) {
        int ch = lc0 + i;
        int po = phys(lr, ch);
        CPASYNC16(base + 0*GT_SZ + po, sa_h + ch*8);
        CPASYNC16(base + 1*GT_SZ + po, sa_l + ch*8);
        CPASYNC16(base + 2*GT_SZ + po, sb_h + ch*8);
        CPASYNC16(base + 3*GT_SZ + po, sb_l + ch*8);
    }
}

__device__ __forceinline__ void gemm_body(const __nv_bfloat16* __restrict__ a_hi,
                                          const __nv_bfloat16* __restrict__ a_lo,
                                          const __nv_bfloat16* __restrict__ b_hi,
                                          const __nv_bfloat16* __restrict__ b_lo,
                                          const float* __restrict__ bias,
                                          __nv_bfloat16* dhi, __nv_bfloat16* dlo,
                                          float* outf)
{
    extern __shared__ char sm[];
    const uint32_t smb = smem_u32(sm);
    const int t = threadIdx.x;
    const int w = t >> 5, lane = t & 31;
    const int wm = w & 3, wn = w >> 2;
    const int m0 = blockIdx.y * 128, n0 = blockIdx.x * 128;

    float acc[2][8][4];
#pragma unroll
    for (int mt = 0; mt < 2; mt++)
#pragma unroll
        for (int nt = 0; nt < 8; nt++)
#pragma unroll
            for (int c = 0; c < 4; c++) acc[mt][nt][c] = 0.f;

    gemm_issue(smb, 0, 0, a_hi, a_lo, b_hi, b_lo, m0, n0, t);
    CP_COMMIT();

    const int aRow = 32*wm + (lane & 15);
    const int aChk = lane >> 4;
    const int bRow = 64*wn + (lane & 7);
    const int bChk = (lane >> 3) & 1;

    for (int c = 0; c < 16; c++) {
        const int buf = c & 1;
        if (c + 1 < 16) {
            gemm_issue(smb, buf ^ 1, c + 1, a_hi, a_lo, b_hi, b_lo, m0, n0, t);
            CP_COMMIT();
            CP_WAIT(1);
        } else {
            CP_WAIT(0);
        }
        __syncthreads();

        uint32_t bAh = smb + buf*GBUF;
        uint32_t bAl = bAh + GT_SZ;
        uint32_t bBh = bAh + 2*GT_SZ;
        uint32_t bBl = bAh + 3*GT_SZ;

#pragma unroll
        for (int j = 0; j < 4; j++) {
            uint32_t ah[2][4], al[2][4];
            ldm_x4(ah[0], bAh + phys(aRow,      2*j + aChk));
            ldm_x4(ah[1], bAh + phys(aRow + 16, 2*j + aChk));
            ldm_x4(al[0], bAl + phys(aRow,      2*j + aChk));
            ldm_x4(al[1], bAl + phys(aRow + 16, 2*j + aChk));
#pragma unroll
            for (int nt = 0; nt < 8; nt++) {
                uint32_t bh[2], bl[2];
                ldm_x2(bh, bBh + phys(bRow + 8*nt, 2*j + bChk));
                ldm_x2(bl, bBl + phys(bRow + 8*nt, 2*j + bChk));
#pragma unroll
                for (int mt = 0; mt < 2; mt++) {
                    mma16816(acc[mt][nt], ah[mt], bh);
                    mma16816(acc[mt][nt], ah[mt], bl);
                    mma16816(acc[mt][nt], al[mt], bh);
                }
            }
        }
        __syncthreads();
    }

    // epilogue
#pragma unroll
    for (int nt = 0; nt < 8; nt++) {
        int col2 = n0 + 64*wn + 8*nt + 2*(lane & 3);
        float2 bb = *reinterpret_cast<const float2*>(bias + col2);
#pragma unroll
        for (int mt = 0; mt < 2; mt++) {
            int row0 = m0 + 32*wm + 16*mt + (lane >> 2);
            int row1 = row0 + 8;
            float v00 = acc[mt][nt][0] + bb.x, v01 = acc[mt][nt][1] + bb.y;
            float v10 = acc[mt][nt][2] + bb.x, v11 = acc[mt][nt][3] + bb.y;
            if (outf) {
                *reinterpret_cast<float2*>(outf + (size_t)row0*DMODEL + col2) = make_float2(v00, v01);
                *reinterpret_cast<float2*>(outf + (size_t)row1*DMODEL + col2) = make_float2(v10, v11);
            } else {
                uint32_t h0 = pack_bf16x2(v00, v01);
                uint32_t l0 = pack_bf16x2(v00 - bf16lo_f(h0), v01 - bf16hi_f(h0));
                uint32_t h1 = pack_bf16x2(v10, v11);
                uint32_t l1 = pack_bf16x2(v10 - bf16lo_f(h1), v11 - bf16hi_f(h1));
                *reinterpret_cast<uint32_t*>(dhi + (size_t)row0*DMODEL + col2) = h0;
                *reinterpret_cast<uint32_t*>(dlo + (size_t)row0*DMODEL + col2) = l0;
                *reinterpret_cast<uint32_t*>(dhi + (size_t)row1*DMODEL + col2) = h1;
                *reinterpret_cast<uint32_t*>(dlo + (size_t)row1*DMODEL + col2) = l1;
            }
        }
    }
}

__global__ __launch_bounds__(256, 1)
void gemm_qkv_kernel(const float* __restrict__ bq,
                     const float* __restrict__ bk,
                     const float* __restrict__ bv)
{
    const int z = blockIdx.z;
    const __nv_bfloat16* ah = (z == 0) ? g_q_hi : (z == 1) ? g_k_hi : g_v_hi;
    const __nv_bfloat16* al = (z == 0) ? g_q_lo : (z == 1) ? g_k_lo : g_v_lo;
    const __nv_bfloat16* bh = g_wt_hi + (size_t)z*DMODEL*DMODEL;
    const __nv_bfloat16* bl = g_wt_lo + (size_t)z*DMODEL*DMODEL;
    const float* bias = (z == 0) ? bq : (z == 1) ? bk : bv;
    __nv_bfloat16* dh = (z == 0) ? g_qp_hi : (z == 1) ? g_kp_hi : g_vp_hi;
    __nv_bfloat16* dl = (z == 0) ? g_qp_lo : (z == 1) ? g_kp_lo : g_vp_lo;
    gemm_body(ah, al, bh, bl, bias, dh, dl, nullptr);
}

__global__ __launch_bounds__(256, 1)
void gemm_o_kernel(const float* __restrict__ bo, float* __restrict__ out)
{
    gemm_body(g_ctx_hi, g_ctx_lo,
              g_wt_hi + (size_t)3*DMODEL*DMODEL, g_wt_lo + (size_t)3*DMODEL*DMODEL,
              bo, nullptr, nullptr, out);
}

// ---------------- flash attention via mma.sync ----------------
// CTA: 4 warps, BQ=64 (16 q-rows per warp), BK=64 per iteration.
#define AT_SZ    8192                  // one 64x64 bf16 tile
#define OFF_QH   0
#define OFF_QL   (AT_SZ)
#define OFF_KV(b) (2*AT_SZ + (b)*4*AT_SZ)
#define ASMEM    (2*AT_SZ + 2*4*AT_SZ) // 81920

__device__ __forceinline__ void attn_issue_kv(uint32_t smb, int buf, int kb,
                                              const __nv_bfloat16* kh,
                                              const __nv_bfloat16* kl,
                                              const __nv_bfloat16* vh,
                                              const __nv_bfloat16* vl,
                                              int t)
{
    const int lr  = t >> 1;
    const int lc0 = (t & 1) * 4;
    size_t srow = (size_t)(kb*64 + lr) * DMODEL;
    uint32_t base = smb + OFF_KV(buf);
#pragma unroll
    for (int i = 0; i < 4; i++) {
        int ch = lc0 + i;
        int po = phys(lr, ch);
        CPASYNC16(base + 0*AT_SZ + po, kh + srow + ch*8);
        CPASYNC16(base + 1*AT_SZ + po, kl + srow + ch*8);
        CPASYNC16(base + 2*AT_SZ + po, vh + srow + ch*8);
        CPASYNC16(base + 3*AT_SZ + po, vl + srow + ch*8);
    }
}

__global__ __launch_bounds__(128, 2)
void attn_kernel()
{
    extern __shared__ char sm[];
    const uint32_t smb = smem_u32(sm);
    const int t = threadIdx.x;
    const int w = t >> 5, lane = t & 31;
    const int b = blockIdx.y >> 4, h = blockIdx.y & 15;
    const int q0 = blockIdx.x * 64;
    const float inv = 1.0f / (sqrtf(64.0f) + 1e-8f);

    const size_t hoff = (size_t)h * HDIM;
    const __nv_bfloat16* qh_g = g_qp_hi + ((size_t)(b*SEQ + q0))*DMODEL + hoff;
    const __nv_bfloat16* ql_g = g_qp_lo + ((size_t)(b*SEQ + q0))*DMODEL + hoff;
    const __nv_bfloat16* kh_g = g_kp_hi + ((size_t)(b*SEQ))*DMODEL + hoff;
    const __nv_bfloat16* kl_g = g_kp_lo + ((size_t)(b*SEQ))*DMODEL + hoff;
    const __nv_bfloat16* vh_g = g_vp_hi + ((size_t)(b*SEQ))*DMODEL + hoff;
    const __nv_bfloat16* vl_g = g_vp_lo + ((size_t)(b*SEQ))*DMODEL + hoff;

    // prologue: Q tiles + KV tile 0, one group
    {
        const int lr  = t >> 1;
        const int lc0 = (t & 1) * 4;
        size_t srow = (size_t)lr * DMODEL;
#pragma unroll
        for (int i = 0; i < 4; i++) {
            int ch = lc0 + i;
            int po = phys(lr, ch);
            CPASYNC16(smb + OFF_QH + po, qh_g + srow + ch*8);
            CPASYNC16(smb + OFF_QL + po, ql_g + srow + ch*8);
        }
        attn_issue_kv(smb, 0, 0, kh_g, kl_g, vh_g, vl_g, t);
        CP_COMMIT();
    }

    uint32_t qh[4][4], ql[4][4];
    float o[8][4];
#pragma unroll
    for (int nt = 0; nt < 8; nt++)
#pragma unroll
        for (int c = 0; c < 4; c++) o[nt][c] = 0.f;
    float m0v = -1e30f, m1v = -1e30f, l0v = 0.f, l1v = 0.f;

    const int r0g = q0 + 16*w + (lane >> 2);   // global q row (low)
    const uint32_t* mbase0 = g_maskbits + ((size_t)b*SEQ + r0g)*MWORDS;
    const uint32_t* mbase1 = mbase0 + 8*MWORDS;

    const int aRow = 16*w + (lane & 15);
    const int aChk = lane >> 4;
    const int kRowL = lane & 7;
    const int kChk  = (lane >> 3) & 1;
    const int vRowL = lane & 15;

    for (int kb = 0; kb < SEQ/64; kb++) {
        const int buf = kb & 1;
        if (kb + 1 < SEQ/64) {
            attn_issue_kv(smb, buf ^ 1, kb + 1, kh_g, kl_g, vh_g, vl_g, t);
            CP_COMMIT();
            CP_WAIT(1);
        } else {
            CP_WAIT(0);
        }
        __syncthreads();

        if (kb == 0) {
#pragma unroll
            for (int j = 0; j < 4; j++) {
                ldm_x4(qh[j], smb + OFF_QH + phys(aRow, 2*j + aChk));
                ldm_x4(ql[j], smb + OFF_QL + phys(aRow, 2*j + aChk));
            }
        }

        uint32_t bKh = smb + OFF_KV(buf);
        uint32_t bKl = bKh + AT_SZ;
        uint32_t bVh = bKh + 2*AT_SZ;
        uint32_t bVl = bKh + 3*AT_SZ;

        // ---- S = Q K^T (3-term split)
        float s[8][4];
#pragma unroll
        for (int nt = 0; nt < 8; nt++)
#pragma unroll
            for (int c = 0; c < 4; c++) s[nt][c] = 0.f;

#pragma unroll
        for (int j = 0; j < 4; j++) {
#pragma unroll
            for (int nt = 0; nt < 8; nt++) {
                uint32_t bh[2], bl[2];
                ldm_x2(bh, bKh + phys(8*nt + kRowL, 2*j + kChk));
                ldm_x2(bl, bKl + phys(8*nt + kRowL, 2*j + kChk));
                mma16816(s[nt], qh[j], bh);
                mma16816(s[nt], qh[j], bl);
                mma16816(s[nt], ql[j], bh);
            }
        }

        // ---- mask + scale (exact reference semantics: -1e9 on masked)
        const int kw = (kb*64) >> 5;
        uint32_t w00 = mbase0[kw], w01 = mbase0[kw+1];
        uint32_t w10 = mbase1[kw], w11 = mbase1[kw+1];
#pragma unroll
        for (int nt = 0; nt < 8; nt++) {
            int nl = 8*nt + 2*(lane & 3);
            uint32_t wr0 = (nl & 32) ? w01 : w00;
            uint32_t wr1 = (nl & 32) ? w11 : w10;
            int sh = nl & 31;
            s[nt][0] = ((wr0 >> sh) & 1)       ? -1e9f : s[nt][0]*inv;
            s[nt][1] = ((wr0 >> (sh+1)) & 1)   ? -1e9f : s[nt][1]*inv;
            s[nt][2] = ((wr1 >> sh) & 1)       ? -1e9f : s[nt][2]*inv;
            s[nt][3] = ((wr1 >> (sh+1)) & 1)   ? -1e9f : s[nt][3]*inv;
        }

        // ---- online softmax (rows r0g, r0g+8 per thread)
        float mx0 = -1e30f, mx1 = -1e30f;
#pragma unroll
        for (int nt = 0; nt < 8; nt++) {
            mx0 = fmaxf(mx0, fmaxf(s[nt][0], s[nt][1]));
            mx1 = fmaxf(mx1, fmaxf(s[nt][2], s[nt][3]));
        }
        mx0 = fmaxf(mx0, __shfl_xor_sync(0xffffffffu, mx0, 1));
        mx0 = fmaxf(mx0, __shfl_xor_sync(0xffffffffu, mx0, 2));
        mx1 = fmaxf(mx1, __shfl_xor_sync(0xffffffffu, mx1, 1));
        mx1 = fmaxf(mx1, __shfl_xor_sync(0xffffffffu, mx1, 2));

        float mn0 = fmaxf(m0v, mx0), mn1 = fmaxf(m1v, mx1);
        float al0 = __expf(m0v - mn0), al1 = __expf(m1v - mn1);
        m0v = mn0; m1v = mn1;

        float ls0 = 0.f, ls1 = 0.f;
#pragma unroll
        for (int nt = 0; nt < 8; nt++) {
            s[nt][0] = __expf(s[nt][0] - mn0);
            s[nt][1] = __expf(s[nt][1] - mn0);
            s[nt][2] = __expf(s[nt][2] - mn1);
            s[nt][3] = __expf(s[nt][3] - mn1);
            ls0 += s[nt][0] + s[nt][1];
            ls1 += s[nt][2] + s[nt][3];
        }
        ls0 += __shfl_xor_sync(0xffffffffu, ls0, 1);
        ls0 += __shfl_xor_sync(0xffffffffu, ls0, 2);
        ls1 += __shfl_xor_sync(0xffffffffu, ls1, 1);
        ls1 += __shfl_xor_sync(0xffffffffu, ls1, 2);
        l0v = l0v*al0 + ls0;
        l1v = l1v*al1 + ls1;

#pragma unroll
        for (int nt = 0; nt < 8; nt++) {
            o[nt][0] *= al0; o[nt][1] *= al0;
            o[nt][2] *= al1; o[nt][3] *= al1;
        }

        // ---- O += P V (P split hi/lo; V via ldmatrix.trans)
#pragma unroll
        for (int j = 0; j < 4; j++) {
            uint32_t ph[4], pl[4];
            // A-frag: a0=(r,klow)=tile2j c0c1; a1=(r+8,klow)=tile2j c2c3;
            //         a2=(r,khigh)=tile2j+1 c0c1; a3=tile2j+1 c2c3
            float e0, e1;
            e0 = s[2*j][0];   e1 = s[2*j][1];
            ph[0] = pack_bf16x2(e0, e1);
            pl[0] = pack_bf16x2(e0 - bf16lo_f(ph[0]), e1 - bf16hi_f(ph[0]));
            e0 = s[2*j][2];   e1 = s[2*j][3];
            ph[1] = pack_bf16x2(e0, e1);
            pl[1] = pack_bf16x2(e0 - bf16lo_f(ph[1]), e1 - bf16hi_f(ph[1]));
            e0 = s[2*j+1][0]; e1 = s[2*j+1][1];
            ph[2] = pack_bf16x2(e0, e1);
            pl[2] = pack_bf16x2(e0 - bf16lo_f(ph[2]), e1 - bf16hi_f(ph[2]));
            e0 = s[2*j+1][2]; e1 = s[2*j+1][3];
            ph[3] = pack_bf16x2(e0, e1);
            pl[3] = pack_bf16x2(e0 - bf16lo_f(ph[3]), e1 - bf16hi_f(ph[3]));
#pragma unroll
            for (int nt = 0; nt < 8; nt++) {
                uint32_t vh[2], vl[2];
                ldm_x2t(vh, bVh + phys(16*j + vRowL, nt));
                ldm_x2t(vl, bVl + phys(16*j + vRowL, nt));
                mma16816(o[nt], ph, vh);
                mma16816(o[nt], ph, vl);
                mma16816(o[nt], pl, vh);
            }
        }
        __syncthreads();
    }

    // ---- finalize: ctx = O / l, write bf16 hi/lo
    float il0 = 1.f / l0v, il1 = 1.f / l1v;
    const size_t row0 = (size_t)(b*SEQ + r0g);
    const size_t row1 = row0 + 8;
#pragma unroll
    for (int nt = 0; nt < 8; nt++) {
        int col = h*64 + 8*nt + 2*(lane & 3);
        float v00 = o[nt][0]*il0, v01 = o[nt][1]*il0;
        float v10 = o[nt][2]*il1, v11 = o[nt][3]*il1;
        uint32_t h0 = pack_bf16x2(v00, v01);
        uint32_t l0 = pack_bf16x2(v00 - bf16lo_f(h0), v01 - bf16hi_f(h0));
        uint32_t h1 = pack_bf16x2(v10, v11);
        uint32_t l1 = pack_bf16x2(v10 - bf16lo_f(h1), v11 - bf16hi_f(h1));
        *reinterpret_cast<uint32_t*>(g_ctx_hi + row0*DMODEL + col) = h0;
        *reinterpret_cast<uint32_t*>(g_ctx_lo + row0*DMODEL + col) = l0;
        *reinterpret_cast<uint32_t*>(g_ctx_hi + row1*DMODEL + col) = h1;
        *reinterpret_cast<uint32_t*>(g_ctx_lo + row1*DMODEL + col) = l1;
    }
}

// ---------------------------------------------------------------------------
extern "C" void kernel_launch(void* const* d_in, const int* in_sizes, int n_in,
                              void* d_out, int out_size)
{
    const float* q    = (const float*)d_in[0];
    const float* k    = (const float*)d_in[1];
    const float* v    = (const float*)d_in[2];
    const int*   mask = (const int*)  d_in[3];
    const float* wq   = (const float*)d_in[4];
    const float* bq   = (const float*)d_in[5];
    const float* wk   = (const float*)d_in[6];
    const float* bk   = (const float*)d_in[7];
    const float* wv   = (const float*)d_in[8];
    const float* bv   = (const float*)d_in[9];
    const float* wo   = (const float*)d_in[10];
    const float* bo   = (const float*)d_in[11];
    float* out = (float*)d_out;

    cudaFuncSetAttribute(gemm_qkv_kernel,
                         cudaFuncAttributeMaxDynamicSharedMemorySize, GSMEM);
    cudaFuncSetAttribute(gemm_o_kernel,
                         cudaFuncAttributeMaxDynamicSharedMemorySize, GSMEM);
    cudaFuncSetAttribute(attn_kernel,
                         cudaFuncAttributeMaxDynamicSharedMemorySize, ASMEM);

    // prep
    dim3 gc(MTOT*DMODEL/4/256, 3);
    cvt_inputs_kernel<<<gc, 256>>>(q, k, v);
    dim3 gw(DMODEL/32, DMODEL/32, 4);
    cvt_w_kernel<<<gw, dim3(32, 8)>>>(wq, wk, wv, wo);
    maskbits_kernel<<<BATCH*SEQ*SEQ/256, 256>>>(mask);

    // qkv projections
    dim3 gg(DMODEL/128, MTOT/128, 3);
    gemm_qkv_kernel<<<gg, 256, GSMEM>>>(bq, bk, bv);

    // attention
    dim3 ga(SEQ/64, BATCH*NHEAD);
    attn_kernel<<<ga, 128, ASMEM>>>();

    // output projection
    dim3 go(DMODEL/128, MTOT/128, 1);
    gemm_o_kernel<<<go, 256, GSMEM>>>(bo, out);
}

// round 6
// speedup vs baseline: 9.1890x; 1.0788x over previous
#include <cuda_runtime.h>
#include <cuda_bf16.h>
#include <cstdint>

#define NHEAD  16
#define DMODEL 1024
#define HDIM   64
#define BATCH  2
#define SEQ    2048
#define MTOT   (BATCH*SEQ)   // 4096
#define MWORDS (SEQ/32)      // 64 mask words per row

// ---------------- device global scratch (allocation-free) ----------------
__device__ __nv_bfloat16 g_q_hi[MTOT*DMODEL],  g_q_lo[MTOT*DMODEL];
__device__ __nv_bfloat16 g_k_hi[MTOT*DMODEL],  g_k_lo[MTOT*DMODEL];
__device__ __nv_bfloat16 g_v_hi[MTOT*DMODEL],  g_v_lo[MTOT*DMODEL];
__device__ __nv_bfloat16 g_wt_hi[4*DMODEL*DMODEL], g_wt_lo[4*DMODEL*DMODEL];
__device__ __nv_bfloat16 g_qp_hi[MTOT*DMODEL], g_qp_lo[MTOT*DMODEL];
__device__ __nv_bfloat16 g_kp_hi[MTOT*DMODEL], g_kp_lo[MTOT*DMODEL];
__device__ __nv_bfloat16 g_vp_hi[MTOT*DMODEL], g_vp_lo[MTOT*DMODEL];
__device__ __nv_bfloat16 g_ctx_hi[MTOT*DMODEL], g_ctx_lo[MTOT*DMODEL];
__device__ uint32_t g_maskbits[BATCH*SEQ*MWORDS];

// ---------------- helpers ----------------
__device__ __forceinline__ uint32_t smem_u32(const void* p) {
    return (uint32_t)__cvta_generic_to_shared(p);
}
__device__ __forceinline__ uint32_t pack_bf16x2(float lo, float hi) {
    uint32_t d;
    asm("cvt.rn.bf16x2.f32 %0, %1, %2;" : "=r"(d) : "f"(hi), "f"(lo));
    return d;
}
__device__ __forceinline__ float bf16lo_f(uint32_t u){ return __uint_as_float(u << 16); }
__device__ __forceinline__ float bf16hi_f(uint32_t u){ return __uint_as_float(u & 0xffff0000u); }

__device__ __forceinline__ void mma16816(float* d, const uint32_t* a, const uint32_t* b) {
    asm volatile("mma.sync.aligned.m16n8k16.row.col.f32.bf16.bf16.f32 "
        "{%0,%1,%2,%3}, {%4,%5,%6,%7}, {%8,%9}, {%0,%1,%2,%3};"
        : "+f"(d[0]), "+f"(d[1]), "+f"(d[2]), "+f"(d[3])
        : "r"(a[0]), "r"(a[1]), "r"(a[2]), "r"(a[3]), "r"(b[0]), "r"(b[1]));
}
__device__ __forceinline__ void ldm_x4(uint32_t* r, uint32_t addr) {
    asm volatile("ldmatrix.sync.aligned.m8n8.x4.shared.b16 {%0,%1,%2,%3}, [%4];"
        : "=r"(r[0]), "=r"(r[1]), "=r"(r[2]), "=r"(r[3]) : "r"(addr));
}
__device__ __forceinline__ void ldm_x2(uint32_t* r, uint32_t addr) {
    asm volatile("ldmatrix.sync.aligned.m8n8.x2.shared.b16 {%0,%1}, [%2];"
        : "=r"(r[0]), "=r"(r[1]) : "r"(addr));
}
__device__ __forceinline__ void ldm_x2t(uint32_t* r, uint32_t addr) {
    asm volatile("ldmatrix.sync.aligned.m8n8.x2.trans.shared.b16 {%0,%1}, [%2];"
        : "=r"(r[0]), "=r"(r[1]) : "r"(addr));
}
#define CPASYNC16(dst, src) \
    asm volatile("cp.async.cg.shared.global [%0], [%1], 16;" :: "r"(dst), "l"(src))
#define CP_COMMIT()   asm volatile("cp.async.commit_group;" ::: "memory")
#define CP_WAIT(n)    asm volatile("cp.async.wait_group %0;" :: "n"(n) : "memory")

// tile with 64 bf16 cols = 128B rows; chunk = 16B unit, XOR swizzle
__device__ __forceinline__ int phys(int row, int chunk) {
    return row*128 + ((chunk ^ (row & 7)) << 4);
}

// ---------------- prep kernels ----------------
__global__ void cvt_inputs_kernel(const float* __restrict__ q,
                                  const float* __restrict__ k,
                                  const float* __restrict__ v)
{
    const int z = blockIdx.y;
    const float* src = (z == 0) ? q : (z == 1) ? k : v;
    __nv_bfloat16* dh = (z == 0) ? g_q_hi : (z == 1) ? g_k_hi : g_v_hi;
    __nv_bfloat16* dl = (z == 0) ? g_q_lo : (z == 1) ? g_k_lo : g_v_lo;
    size_t i = (size_t)blockIdx.x*256 + threadIdx.x;   // 1 float4 each
    float4 x = reinterpret_cast<const float4*>(src)[i];
    uint32_t h0 = pack_bf16x2(x.x, x.y);
    uint32_t h1 = pack_bf16x2(x.z, x.w);
    uint32_t l0 = pack_bf16x2(x.x - bf16lo_f(h0), x.y - bf16hi_f(h0));
    uint32_t l1 = pack_bf16x2(x.z - bf16lo_f(h1), x.w - bf16hi_f(h1));
    reinterpret_cast<uint2*>(dh)[i] = make_uint2(h0, h1);
    reinterpret_cast<uint2*>(dl)[i] = make_uint2(l0, l1);
}

__global__ void cvt_w_kernel(const float* __restrict__ wq,
                             const float* __restrict__ wk,
                             const float* __restrict__ wv,
                             const float* __restrict__ wo)
{
    __shared__ float ts[32][33];
    const int wsel = blockIdx.z;
    const float* W = (wsel == 0) ? wq : (wsel == 1) ? wk : (wsel == 2) ? wv : wo;
    const int k0 = blockIdx.x*32, n0 = blockIdx.y*32;
    const int tx = threadIdx.x, ty = threadIdx.y;
#pragma unroll
    for (int i = 0; i < 4; i++)
        ts[ty + 8*i][tx] = W[(size_t)(k0 + ty + 8*i)*DMODEL + n0 + tx];
    __syncthreads();
    __nv_bfloat16* dh = g_wt_hi + (size_t)wsel*DMODEL*DMODEL;
    __nv_bfloat16* dl = g_wt_lo + (size_t)wsel*DMODEL*DMODEL;
#pragma unroll
    for (int i = 0; i < 4; i++) {
        float x = ts[tx][ty + 8*i];
        __nv_bfloat16 h = __float2bfloat16(x);
        float r = x - __bfloat162float(h);
        size_t o = (size_t)(n0 + ty + 8*i)*DMODEL + k0 + tx;
        dh[o] = h;
        dl[o] = __float2bfloat16(r);
    }
}

__global__ void maskbits_kernel(const int* __restrict__ mask)
{
    size_t i = (size_t)blockIdx.x*256 + threadIdx.x;
    int v = mask[i];
    uint32_t bits = __ballot_sync(0xffffffffu, v != 0);
    if ((threadIdx.x & 31) == 0) g_maskbits[i >> 5] = bits;
}

// ---------------- GEMM via mma.sync (bf16 hi/lo split) ----------------
// C[M,N] = A[M,K] @ W[K,N] + bias.  CTA 128x128, 16 warps (32x32 each), KC=64.
#define GT_SZ  16384
#define GBUF   (4*GT_SZ)
#define GSMEM  (2*GBUF)   // 131072
#define GEMM_THREADS 512

__device__ __forceinline__ void gemm_issue(uint32_t smb, int buf, int c,
                                           const __nv_bfloat16* a_hi,
                                           const __nv_bfloat16* a_lo,
                                           const __nv_bfloat16* b_hi,
                                           const __nv_bfloat16* b_lo,
                                           int m0, int n0, int t)
{
    const int lr  = t >> 2;            // 0..127
    const int lc0 = (t & 3) << 1;      // chunk base {0,2,4,6}
    const int k0  = c * 64;
    const __nv_bfloat16* sa_h = a_hi + (size_t)(m0 + lr)*DMODEL + k0;
    const __nv_bfloat16* sa_l = a_lo + (size_t)(m0 + lr)*DMODEL + k0;
    const __nv_bfloat16* sb_h = b_hi + (size_t)(n0 + lr)*DMODEL + k0;
    const __nv_bfloat16* sb_l = b_lo + (size_t)(n0 + lr)*DMODEL + k0;
    uint32_t base = smb + buf*GBUF;
#pragma unroll
    for (int i = 0; i < 2; i++) {
        int ch = lc0 + i;
        int po = phys(lr, ch);
        CPASYNC16(base + 0*GT_SZ + po, sa_h + ch*8);
        CPASYNC16(base + 1*GT_SZ + po, sa_l + ch*8);
        CPASYNC16(base + 2*GT_SZ + po, sb_h + ch*8);
        CPASYNC16(base + 3*GT_SZ + po, sb_l + ch*8);
    }
}

__device__ __forceinline__ void gemm_body(const __nv_bfloat16* __restrict__ a_hi,
                                          const __nv_bfloat16* __restrict__ a_lo,
                                          const __nv_bfloat16* __restrict__ b_hi,
                                          const __nv_bfloat16* __restrict__ b_lo,
                                          const float* __restrict__ bias,
                                          __nv_bfloat16* dhi, __nv_bfloat16* dlo,
                                          float* outf)
{
    extern __shared__ char sm[];
    const uint32_t smb = smem_u32(sm);
    const int t = threadIdx.x;
    const int w = t >> 5, lane = t & 31;
    const int wm = w & 3, wn = w >> 2;        // 4x4 warp grid, 32x32 tiles
    const int m0 = blockIdx.y * 128, n0 = blockIdx.x * 128;

    float acc[2][4][4];
#pragma unroll
    for (int mt = 0; mt < 2; mt++)
#pragma unroll
        for (int nt = 0; nt < 4; nt++)
#pragma unroll
            for (int c = 0; c < 4; c++) acc[mt][nt][c] = 0.f;

    gemm_issue(smb, 0, 0, a_hi, a_lo, b_hi, b_lo, m0, n0, t);
    CP_COMMIT();

    const int aRow = 32*wm + (lane & 15);
    const int aChk = lane >> 4;
    // B x4 addressing: lanes 0-7 -> (rows+0, c0), 8-15 -> (rows+0, c1),
    //                  16-23 -> (rows+8, c0), 24-31 -> (rows+8, c1)
    const int bRowOff = ((lane >> 4) & 1)*8 + (lane & 7);
    const int bChkOff = (lane >> 3) & 1;

    for (int c = 0; c < 16; c++) {
        const int buf = c & 1;
        if (c + 1 < 16) {
            gemm_issue(smb, buf ^ 1, c + 1, a_hi, a_lo, b_hi, b_lo, m0, n0, t);
            CP_COMMIT();
            CP_WAIT(1);
        } else {
            CP_WAIT(0);
        }
        __syncthreads();

        uint32_t bAh = smb + buf*GBUF;
        uint32_t bAl = bAh + GT_SZ;
        uint32_t bBh = bAh + 2*GT_SZ;
        uint32_t bBl = bAh + 3*GT_SZ;

#pragma unroll
        for (int j = 0; j < 4; j++) {
            uint32_t ah[2][4], al[2][4];
            ldm_x4(ah[0], bAh + phys(aRow,      2*j + aChk));
            ldm_x4(ah[1], bAh + phys(aRow + 16, 2*j + aChk));
            ldm_x4(al[0], bAl + phys(aRow,      2*j + aChk));
            ldm_x4(al[1], bAl + phys(aRow + 16, 2*j + aChk));
            uint32_t bh[2][4], bl[2][4];
#pragma unroll
            for (int p = 0; p < 2; p++) {
                int br = 32*wn + 16*p + bRowOff;
                ldm_x4(bh[p], bBh + phys(br, 2*j + bChkOff));
                ldm_x4(bl[p], bBl + phys(br, 2*j + bChkOff));
            }
#pragma unroll
            for (int nt = 0; nt < 4; nt++) {
                const uint32_t* Bh = &bh[nt >> 1][(nt & 1)*2];
                const uint32_t* Bl = &bl[nt >> 1][(nt & 1)*2];
#pragma unroll
                for (int mt = 0; mt < 2; mt++) {
                    mma16816(acc[mt][nt], ah[mt], Bh);
                    mma16816(acc[mt][nt], ah[mt], Bl);
                    mma16816(acc[mt][nt], al[mt], Bh);
                }
            }
        }
        __syncthreads();
    }

    // epilogue
#pragma unroll
    for (int nt = 0; nt < 4; nt++) {
        int col2 = n0 + 32*wn + 8*nt + 2*(lane & 3);
        float2 bb = *reinterpret_cast<const float2*>(bias + col2);
#pragma unroll
        for (int mt = 0; mt < 2; mt++) {
            int row0 = m0 + 32*wm + 16*mt + (lane >> 2);
            int row1 = row0 + 8;
            float v00 = acc[mt][nt][0] + bb.x, v01 = acc[mt][nt][1] + bb.y;
            float v10 = acc[mt][nt][2] + bb.x, v11 = acc[mt][nt][3] + bb.y;
            if (outf) {
                *reinterpret_cast<float2*>(outf + (size_t)row0*DMODEL + col2) = make_float2(v00, v01);
                *reinterpret_cast<float2*>(outf + (size_t)row1*DMODEL + col2) = make_float2(v10, v11);
            } else {
                uint32_t h0 = pack_bf16x2(v00, v01);
                uint32_t l0 = pack_bf16x2(v00 - bf16lo_f(h0), v01 - bf16hi_f(h0));
                uint32_t h1 = pack_bf16x2(v10, v11);
                uint32_t l1 = pack_bf16x2(v10 - bf16lo_f(h1), v11 - bf16hi_f(h1));
                *reinterpret_cast<uint32_t*>(dhi + (size_t)row0*DMODEL + col2) = h0;
                *reinterpret_cast<uint32_t*>(dlo + (size_t)row0*DMODEL + col2) = l0;
                *reinterpret_cast<uint32_t*>(dhi + (size_t)row1*DMODEL + col2) = h1;
                *reinterpret_cast<uint32_t*>(dlo + (size_t)row1*DMODEL + col2) = l1;
            }
        }
    }
}

__global__ __launch_bounds__(GEMM_THREADS, 1)
void gemm_qkv_kernel(const float* __restrict__ bq,
                     const float* __restrict__ bk,
                     const float* __restrict__ bv)
{
    const int z = blockIdx.z;
    const __nv_bfloat16* ah = (z == 0) ? g_q_hi : (z == 1) ? g_k_hi : g_v_hi;
    const __nv_bfloat16* al = (z == 0) ? g_q_lo : (z == 1) ? g_k_lo : g_v_lo;
    const __nv_bfloat16* bh = g_wt_hi + (size_t)z*DMODEL*DMODEL;
    const __nv_bfloat16* bl = g_wt_lo + (size_t)z*DMODEL*DMODEL;
    const float* bias = (z == 0) ? bq : (z == 1) ? bk : bv;
    __nv_bfloat16* dh = (z == 0) ? g_qp_hi : (z == 1) ? g_kp_hi : g_vp_hi;
    __nv_bfloat16* dl = (z == 0) ? g_qp_lo : (z == 1) ? g_kp_lo : g_vp_lo;
    gemm_body(ah, al, bh, bl, bias, dh, dl, nullptr);
}

__global__ __launch_bounds__(GEMM_THREADS, 1)
void gemm_o_kernel(const float* __restrict__ bo, float* __restrict__ out)
{
    gemm_body(g_ctx_hi, g_ctx_lo,
              g_wt_hi + (size_t)3*DMODEL*DMODEL, g_wt_lo + (size_t)3*DMODEL*DMODEL,
              bo, nullptr, nullptr, out);
}

// ---------------- flash attention via mma.sync ----------------
// CTA: 8 warps, BQ=128 (16 q-rows per warp), BK=64 per iteration, 2 CTAs/SM.
#define AT_SZ    8192                  // one 64x64 bf16 tile
#define QT_SZ    16384                 // 128x64 bf16 tile
#define OFF_QH   0
#define OFF_QL   (QT_SZ)
#define OFF_KV(b) (2*QT_SZ + (b)*4*AT_SZ)
#define ASMEM    (2*QT_SZ + 2*4*AT_SZ) // 98304

__device__ __forceinline__ void attn_issue_kv(uint32_t smb, int buf, int kb,
                                              const __nv_bfloat16* kh,
                                              const __nv_bfloat16* kl,
                                              const __nv_bfloat16* vh,
                                              const __nv_bfloat16* vl,
                                              int t)
{
    const int lr  = t >> 2;            // 0..63
    const int lc0 = (t & 3) << 1;      // {0,2,4,6}
    size_t srow = (size_t)(kb*64 + lr) * DMODEL;
    uint32_t base = smb + OFF_KV(buf);
#pragma unroll
    for (int i = 0; i < 2; i++) {
        int ch = lc0 + i;
        int po = phys(lr, ch);
        CPASYNC16(base + 0*AT_SZ + po, kh + srow + ch*8);
        CPASYNC16(base + 1*AT_SZ + po, kl + srow + ch*8);
        CPASYNC16(base + 2*AT_SZ + po, vh + srow + ch*8);
        CPASYNC16(base + 3*AT_SZ + po, vl + srow + ch*8);
    }
}

__global__ __launch_bounds__(256, 2)
void attn_kernel()
{
    extern __shared__ char sm[];
    const uint32_t smb = smem_u32(sm);
    const int t = threadIdx.x;
    const int w = t >> 5, lane = t & 31;
    const int b = blockIdx.y >> 4, h = blockIdx.y & 15;
    const int q0 = blockIdx.x * 128;
    const float inv = 1.0f / (sqrtf(64.0f) + 1e-8f);

    const size_t hoff = (size_t)h * HDIM;
    const __nv_bfloat16* qh_g = g_qp_hi + ((size_t)(b*SEQ + q0))*DMODEL + hoff;
    const __nv_bfloat16* ql_g = g_qp_lo + ((size_t)(b*SEQ + q0))*DMODEL + hoff;
    const __nv_bfloat16* kh_g = g_kp_hi + ((size_t)(b*SEQ))*DMODEL + hoff;
    const __nv_bfloat16* kl_g = g_kp_lo + ((size_t)(b*SEQ))*DMODEL + hoff;
    const __nv_bfloat16* vh_g = g_vp_hi + ((size_t)(b*SEQ))*DMODEL + hoff;
    const __nv_bfloat16* vl_g = g_vp_lo + ((size_t)(b*SEQ))*DMODEL + hoff;

    // prologue: Q tiles (128 rows) + KV tile 0
    {
        const int lr  = t >> 1;        // 0..127
        const int lc0 = (t & 1) << 2;  // {0,4}
        size_t srow = (size_t)lr * DMODEL;
#pragma unroll
        for (int i = 0; i < 4; i++) {
            int ch = lc0 + i;
            int po = phys(lr, ch);
            CPASYNC16(smb + OFF_QH + po, qh_g + srow + ch*8);
            CPASYNC16(smb + OFF_QL + po, ql_g + srow + ch*8);
        }
        attn_issue_kv(smb, 0, 0, kh_g, kl_g, vh_g, vl_g, t);
        CP_COMMIT();
    }

    uint32_t qh[4][4], ql[4][4];
    float o[8][4];
#pragma unroll
    for (int nt = 0; nt < 8; nt++)
#pragma unroll
        for (int c = 0; c < 4; c++) o[nt][c] = 0.f;
    float m0v = -1e30f, m1v = -1e30f, l0v = 0.f, l1v = 0.f;

    const int r0g = q0 + 16*w + (lane >> 2);   // global q row (low)
    const uint32_t* mbase0 = g_maskbits + ((size_t)b*SEQ + r0g)*MWORDS;
    const uint32_t* mbase1 = mbase0 + 8*MWORDS;

    const int aRow = 16*w + (lane & 15);
    const int aChk = lane >> 4;
    const int kRowL = lane & 7;
    const int kChk  = (lane >> 3) & 1;
    const int vRowL = lane & 15;

    for (int kb = 0; kb < SEQ/64; kb++) {
        const int buf = kb & 1;
        if (kb + 1 < SEQ/64) {
            attn_issue_kv(smb, buf ^ 1, kb + 1, kh_g, kl_g, vh_g, vl_g, t);
            CP_COMMIT();
            CP_WAIT(1);
        } else {
            CP_WAIT(0);
        }
        __syncthreads();

        if (kb == 0) {
#pragma unroll
            for (int j = 0; j < 4; j++) {
                ldm_x4(qh[j], smb + OFF_QH + phys(aRow, 2*j + aChk));
                ldm_x4(ql[j], smb + OFF_QL + phys(aRow, 2*j + aChk));
            }
        }

        uint32_t bKh = smb + OFF_KV(buf);
        uint32_t bKl = bKh + AT_SZ;
        uint32_t bVh = bKh + 2*AT_SZ;
        uint32_t bVl = bKh + 3*AT_SZ;

        // ---- S = Q K^T (3-term split)
        float s[8][4];
#pragma unroll
        for (int nt = 0; nt < 8; nt++)
#pragma unroll
            for (int c = 0; c < 4; c++) s[nt][c] = 0.f;

#pragma unroll
        for (int j = 0; j < 4; j++) {
#pragma unroll
            for (int nt = 0; nt < 8; nt++) {
                uint32_t bh[2], bl[2];
                ldm_x2(bh, bKh + phys(8*nt + kRowL, 2*j + kChk));
                ldm_x2(bl, bKl + phys(8*nt + kRowL, 2*j + kChk));
                mma16816(s[nt], qh[j], bh);
                mma16816(s[nt], qh[j], bl);
                mma16816(s[nt], ql[j], bh);
            }
        }

        // ---- mask + scale (exact reference semantics: -1e9 on masked)
        const int kw = (kb*64) >> 5;
        uint32_t w00 = mbase0[kw], w01 = mbase0[kw+1];
        uint32_t w10 = mbase1[kw], w11 = mbase1[kw+1];
#pragma unroll
        for (int nt = 0; nt < 8; nt++) {
            int nl = 8*nt + 2*(lane & 3);
            uint32_t wr0 = (nl & 32) ? w01 : w00;
            uint32_t wr1 = (nl & 32) ? w11 : w10;
            int sh = nl & 31;
            s[nt][0] = ((wr0 >> sh) & 1)       ? -1e9f : s[nt][0]*inv;
            s[nt][1] = ((wr0 >> (sh+1)) & 1)   ? -1e9f : s[nt][1]*inv;
            s[nt][2] = ((wr1 >> sh) & 1)       ? -1e9f : s[nt][2]*inv;
            s[nt][3] = ((wr1 >> (sh+1)) & 1)   ? -1e9f : s[nt][3]*inv;
        }

        // ---- online softmax (rows r0g, r0g+8 per thread)
        float mx0 = -1e30f, mx1 = -1e30f;
#pragma unroll
        for (int nt = 0; nt < 8; nt++) {
            mx0 = fmaxf(mx0, fmaxf(s[nt][0], s[nt][1]));
            mx1 = fmaxf(mx1, fmaxf(s[nt][2], s[nt][3]));
        }
        mx0 = fmaxf(mx0, __shfl_xor_sync(0xffffffffu, mx0, 1));
        mx0 = fmaxf(mx0, __shfl_xor_sync(0xffffffffu, mx0, 2));
        mx1 = fmaxf(mx1, __shfl_xor_sync(0xffffffffu, mx1, 1));
        mx1 = fmaxf(mx1, __shfl_xor_sync(0xffffffffu, mx1, 2));

        float mn0 = fmaxf(m0v, mx0), mn1 = fmaxf(m1v, mx1);
        float al0 = __expf(m0v - mn0), al1 = __expf(m1v - mn1);
        m0v = mn0; m1v = mn1;

        float ls0 = 0.f, ls1 = 0.f;
#pragma unroll
        for (int nt = 0; nt < 8; nt++) {
            s[nt][0] = __expf(s[nt][0] - mn0);
            s[nt][1] = __expf(s[nt][1] - mn0);
            s[nt][2] = __expf(s[nt][2] - mn1);
            s[nt][3] = __expf(s[nt][3] - mn1);
            ls0 += s[nt][0] + s[nt][1];
            ls1 += s[nt][2] + s[nt][3];
        }
        ls0 += __shfl_xor_sync(0xffffffffu, ls0, 1);
        ls0 += __shfl_xor_sync(0xffffffffu, ls0, 2);
        ls1 += __shfl_xor_sync(0xffffffffu, ls1, 1);
        ls1 += __shfl_xor_sync(0xffffffffu, ls1, 2);
        l0v = l0v*al0 + ls0;
        l1v = l1v*al1 + ls1;

#pragma unroll
        for (int nt = 0; nt < 8; nt++) {
            o[nt][0] *= al0; o[nt][1] *= al0;
            o[nt][2] *= al1; o[nt][3] *= al1;
        }

        // ---- O += P V (P split hi/lo; V via ldmatrix.trans)
#pragma unroll
        for (int j = 0; j < 4; j++) {
            uint32_t ph[4], pl[4];
            float e0, e1;
            e0 = s[2*j][0];   e1 = s[2*j][1];
            ph[0] = pack_bf16x2(e0, e1);
            pl[0] = pack_bf16x2(e0 - bf16lo_f(ph[0]), e1 - bf16hi_f(ph[0]));
            e0 = s[2*j][2];   e1 = s[2*j][3];
            ph[1] = pack_bf16x2(e0, e1);
            pl[1] = pack_bf16x2(e0 - bf16lo_f(ph[1]), e1 - bf16hi_f(ph[1]));
            e0 = s[2*j+1][0]; e1 = s[2*j+1][1];
            ph[2] = pack_bf16x2(e0, e1);
            pl[2] = pack_bf16x2(e0 - bf16lo_f(ph[2]), e1 - bf16hi_f(ph[2]));
            e0 = s[2*j+1][2]; e1 = s[2*j+1][3];
            ph[3] = pack_bf16x2(e0, e1);
            pl[3] = pack_bf16x2(e0 - bf16lo_f(ph[3]), e1 - bf16hi_f(ph[3]));
#pragma unroll
            for (int nt = 0; nt < 8; nt++) {
                uint32_t vh[2], vl[2];
                ldm_x2t(vh, bVh + phys(16*j + vRowL, nt));
                ldm_x2t(vl, bVl + phys(16*j + vRowL, nt));
                mma16816(o[nt], ph, vh);
                mma16816(o[nt], ph, vl);
                mma16816(o[nt], pl, vh);
            }
        }
        __syncthreads();
    }

    // ---- finalize: ctx = O / l, write bf16 hi/lo
    float il0 = 1.f / l0v, il1 = 1.f / l1v;
    const size_t row0 = (size_t)(b*SEQ + r0g);
    const size_t row1 = row0 + 8;
#pragma unroll
    for (int nt = 0; nt < 8; nt++) {
        int col = h*64 + 8*nt + 2*(lane & 3);
        float v00 = o[nt][0]*il0, v01 = o[nt][1]*il0;
        float v10 = o[nt][2]*il1, v11 = o[nt][3]*il1;
        uint32_t h0 = pack_bf16x2(v00, v01);
        uint32_t l0 = pack_bf16x2(v00 - bf16lo_f(h0), v01 - bf16hi_f(h0));
        uint32_t h1 = pack_bf16x2(v10, v11);
        uint32_t l1 = pack_bf16x2(v10 - bf16lo_f(h1), v11 - bf16hi_f(h1));
        *reinterpret_cast<uint32_t*>(g_ctx_hi + row0*DMODEL + col) = h0;
        *reinterpret_cast<uint32_t*>(g_ctx_lo + row0*DMODEL + col) = l0;
        *reinterpret_cast<uint32_t*>(g_ctx_hi + row1*DMODEL + col) = h1;
        *reinterpret_cast<uint32_t*>(g_ctx_lo + row1*DMODEL + col) = l1;
    }
}

// ---------------------------------------------------------------------------
extern "C" void kernel_launch(void* const* d_in, const int* in_sizes, int n_in,
                              void* d_out, int out_size)
{
    const float* q    = (const float*)d_in[0];
    const float* k    = (const float*)d_in[1];
    const float* v    = (const float*)d_in[2];
    const int*   mask = (const int*)  d_in[3];
    const float* wq   = (const float*)d_in[4];
    const float* bq   = (const float*)d_in[5];
    const float* wk   = (const float*)d_in[6];
    const float* bk   = (const float*)d_in[7];
    const float* wv   = (const float*)d_in[8];
    const float* bv   = (const float*)d_in[9];
    const float* wo   = (const float*)d_in[10];
    const float* bo   = (const float*)d_in[11];
    float* out = (float*)d_out;

    cudaFuncSetAttribute(gemm_qkv_kernel,
                         cudaFuncAttributeMaxDynamicSharedMemorySize, GSMEM);
    cudaFuncSetAttribute(gemm_o_kernel,
                         cudaFuncAttributeMaxDynamicSharedMemorySize, GSMEM);
    cudaFuncSetAttribute(attn_kernel,
                         cudaFuncAttributeMaxDynamicSharedMemorySize, ASMEM);

    // prep
    dim3 gc(MTOT*DMODEL/4/256, 3);
    cvt_inputs_kernel<<<gc, 256>>>(q, k, v);
    dim3 gw(DMODEL/32, DMODEL/32, 4);
    cvt_w_kernel<<<gw, dim3(32, 8)>>>(wq, wk, wv, wo);
    maskbits_kernel<<<BATCH*SEQ*SEQ/256, 256>>>(mask);

    // qkv projections
    dim3 gg(DMODEL/128, MTOT/128, 3);
    gemm_qkv_kernel<<<gg, GEMM_THREADS, GSMEM>>>(bq, bk, bv);

    // attention
    dim3 ga(SEQ/128, BATCH*NHEAD);
    attn_kernel<<<ga, 256, ASMEM>>>();

    // output projection
    dim3 go(DMODEL/128, MTOT/128, 1);
    gemm_o_kernel<<<go, GEMM_THREADS, GSMEM>>>(bo, out);
}

// round 7
// speedup vs baseline: 9.4312x; 1.0264x over previous
#include <cuda_runtime.h>
#include <cuda_bf16.h>
#include <cstdint>

#define NHEAD  16
#define DMODEL 1024
#define HDIM   64
#define BATCH  2
#define SEQ    2048
#define MTOT   (BATCH*SEQ)   // 4096
#define MWORDS (SEQ/32)      // 64 mask words per row

// ---------------- device global scratch (allocation-free) ----------------
__device__ __nv_bfloat16 g_q_hi[MTOT*DMODEL],  g_q_lo[MTOT*DMODEL];
__device__ __nv_bfloat16 g_k_hi[MTOT*DMODEL],  g_k_lo[MTOT*DMODEL];
__device__ __nv_bfloat16 g_v_hi[MTOT*DMODEL],  g_v_lo[MTOT*DMODEL];
__device__ __nv_bfloat16 g_wt_hi[4*DMODEL*DMODEL], g_wt_lo[4*DMODEL*DMODEL];
__device__ __nv_bfloat16 g_qp_hi[MTOT*DMODEL], g_qp_lo[MTOT*DMODEL];
__device__ __nv_bfloat16 g_kp_hi[MTOT*DMODEL], g_kp_lo[MTOT*DMODEL];
__device__ __nv_bfloat16 g_vp_hi[MTOT*DMODEL], g_vp_lo[MTOT*DMODEL];
__device__ __nv_bfloat16 g_ctx_hi[MTOT*DMODEL], g_ctx_lo[MTOT*DMODEL];
__device__ uint32_t g_maskbits[BATCH*SEQ*MWORDS];

// ---------------- helpers ----------------
__device__ __forceinline__ uint32_t smem_u32(const void* p) {
    return (uint32_t)__cvta_generic_to_shared(p);
}
__device__ __forceinline__ uint32_t pack_bf16x2(float lo, float hi) {
    uint32_t d;
    asm("cvt.rn.bf16x2.f32 %0, %1, %2;" : "=r"(d) : "f"(hi), "f"(lo));
    return d;
}
__device__ __forceinline__ float bf16lo_f(uint32_t u){ return __uint_as_float(u << 16); }
__device__ __forceinline__ float bf16hi_f(uint32_t u){ return __uint_as_float(u & 0xffff0000u); }

__device__ __forceinline__ void mma16816(float* d, const uint32_t* a, const uint32_t* b) {
    asm volatile("mma.sync.aligned.m16n8k16.row.col.f32.bf16.bf16.f32 "
        "{%0,%1,%2,%3}, {%4,%5,%6,%7}, {%8,%9}, {%0,%1,%2,%3};"
        : "+f"(d[0]), "+f"(d[1]), "+f"(d[2]), "+f"(d[3])
        : "r"(a[0]), "r"(a[1]), "r"(a[2]), "r"(a[3]), "r"(b[0]), "r"(b[1]));
}
__device__ __forceinline__ void ldm_x4(uint32_t* r, uint32_t addr) {
    asm volatile("ldmatrix.sync.aligned.m8n8.x4.shared.b16 {%0,%1,%2,%3}, [%4];"
        : "=r"(r[0]), "=r"(r[1]), "=r"(r[2]), "=r"(r[3]) : "r"(addr));
}
__device__ __forceinline__ void ldm_x4t(uint32_t* r, uint32_t addr) {
    asm volatile("ldmatrix.sync.aligned.m8n8.x4.trans.shared.b16 {%0,%1,%2,%3}, [%4];"
        : "=r"(r[0]), "=r"(r[1]), "=r"(r[2]), "=r"(r[3]) : "r"(addr));
}
#define CPASYNC16(dst, src) \
    asm volatile("cp.async.cg.shared.global [%0], [%1], 16;" :: "r"(dst), "l"(src))
#define CP_COMMIT()   asm volatile("cp.async.commit_group;" ::: "memory")
#define CP_WAIT(n)    asm volatile("cp.async.wait_group %0;" :: "n"(n) : "memory")

// tile with 64 bf16 cols = 128B rows; chunk = 16B unit, XOR swizzle
__device__ __forceinline__ int phys(int row, int chunk) {
    return row*128 + ((chunk ^ (row & 7)) << 4);
}

// ---------------- prep kernels ----------------
__global__ void cvt_inputs_kernel(const float* __restrict__ q,
                                  const float* __restrict__ k,
                                  const float* __restrict__ v)
{
    const int z = blockIdx.y;
    const float* src = (z == 0) ? q : (z == 1) ? k : v;
    __nv_bfloat16* dh = (z == 0) ? g_q_hi : (z == 1) ? g_k_hi : g_v_hi;
    __nv_bfloat16* dl = (z == 0) ? g_q_lo : (z == 1) ? g_k_lo : g_v_lo;
    size_t i = (size_t)blockIdx.x*256 + threadIdx.x;   // 1 float4 each
    float4 x = reinterpret_cast<const float4*>(src)[i];
    uint32_t h0 = pack_bf16x2(x.x, x.y);
    uint32_t h1 = pack_bf16x2(x.z, x.w);
    uint32_t l0 = pack_bf16x2(x.x - bf16lo_f(h0), x.y - bf16hi_f(h0));
    uint32_t l1 = pack_bf16x2(x.z - bf16lo_f(h1), x.w - bf16hi_f(h1));
    reinterpret_cast<uint2*>(dh)[i] = make_uint2(h0, h1);
    reinterpret_cast<uint2*>(dl)[i] = make_uint2(l0, l1);
}

__global__ void cvt_w_kernel(const float* __restrict__ wq,
                             const float* __restrict__ wk,
                             const float* __restrict__ wv,
                             const float* __restrict__ wo)
{
    __shared__ float ts[32][33];
    const int wsel = blockIdx.z;
    const float* W = (wsel == 0) ? wq : (wsel == 1) ? wk : (wsel == 2) ? wv : wo;
    const int k0 = blockIdx.x*32, n0 = blockIdx.y*32;
    const int tx = threadIdx.x, ty = threadIdx.y;
#pragma unroll
    for (int i = 0; i < 4; i++)
        ts[ty + 8*i][tx] = W[(size_t)(k0 + ty + 8*i)*DMODEL + n0 + tx];
    __syncthreads();
    __nv_bfloat16* dh = g_wt_hi + (size_t)wsel*DMODEL*DMODEL;
    __nv_bfloat16* dl = g_wt_lo + (size_t)wsel*DMODEL*DMODEL;
#pragma unroll
    for (int i = 0; i < 4; i++) {
        float x = ts[tx][ty + 8*i];
        __nv_bfloat16 h = __float2bfloat16(x);
        float r = x - __bfloat162float(h);
        size_t o = (size_t)(n0 + ty + 8*i)*DMODEL + k0 + tx;
        dh[o] = h;
        dl[o] = __float2bfloat16(r);
    }
}

__global__ void maskbits_kernel(const int* __restrict__ mask)
{
    size_t i = (size_t)blockIdx.x*256 + threadIdx.x;
    int v = mask[i];
    uint32_t bits = __ballot_sync(0xffffffffu, v != 0);
    if ((threadIdx.x & 31) == 0) g_maskbits[i >> 5] = bits;
}

// ---------------- GEMM via mma.sync (bf16 hi/lo split) ----------------
// C[M,N] = A[M,K] @ W[K,N] + bias.  CTA 128x128, 16 warps (32x32 each),
// KC=64, 3-stage cp.async pipeline, ONE barrier per chunk.
#define GT_SZ  16384
#define GBUF   (4*GT_SZ)
#define GSTAGES 3
#define GSMEM  (GSTAGES*GBUF)   // 196608
#define GEMM_THREADS 512
#define NCHUNK 16

__device__ __forceinline__ void gemm_issue(uint32_t smb, int buf, int c,
                                           const __nv_bfloat16* a_hi,
                                           const __nv_bfloat16* a_lo,
                                           const __nv_bfloat16* b_hi,
                                           const __nv_bfloat16* b_lo,
                                           int m0, int n0, int t)
{
    const int lr  = t >> 2;            // 0..127
    const int lc0 = (t & 3) << 1;      // chunk base {0,2,4,6}
    const int k0  = c * 64;
    const __nv_bfloat16* sa_h = a_hi + (size_t)(m0 + lr)*DMODEL + k0;
    const __nv_bfloat16* sa_l = a_lo + (size_t)(m0 + lr)*DMODEL + k0;
    const __nv_bfloat16* sb_h = b_hi + (size_t)(n0 + lr)*DMODEL + k0;
    const __nv_bfloat16* sb_l = b_lo + (size_t)(n0 + lr)*DMODEL + k0;
    uint32_t base = smb + buf*GBUF;
#pragma unroll
    for (int i = 0; i < 2; i++) {
        int ch = lc0 + i;
        int po = phys(lr, ch);
        CPASYNC16(base + 0*GT_SZ + po, sa_h + ch*8);
        CPASYNC16(base + 1*GT_SZ + po, sa_l + ch*8);
        CPASYNC16(base + 2*GT_SZ + po, sb_h + ch*8);
        CPASYNC16(base + 3*GT_SZ + po, sb_l + ch*8);
    }
}

__device__ __forceinline__ void gemm_body(const __nv_bfloat16* __restrict__ a_hi,
                                          const __nv_bfloat16* __restrict__ a_lo,
                                          const __nv_bfloat16* __restrict__ b_hi,
                                          const __nv_bfloat16* __restrict__ b_lo,
                                          const float* __restrict__ bias,
                                          __nv_bfloat16* dhi, __nv_bfloat16* dlo,
                                          float* outf)
{
    extern __shared__ char sm[];
    const uint32_t smb = smem_u32(sm);
    const int t = threadIdx.x;
    const int w = t >> 5, lane = t & 31;
    const int wm = w & 3, wn = w >> 2;        // 4x4 warp grid, 32x32 tiles
    const int m0 = blockIdx.y * 128, n0 = blockIdx.x * 128;

    float acc[2][4][4];
#pragma unroll
    for (int mt = 0; mt < 2; mt++)
#pragma unroll
        for (int nt = 0; nt < 4; nt++)
#pragma unroll
            for (int c = 0; c < 4; c++) acc[mt][nt][c] = 0.f;

    // prologue: 2 chunks in flight
    gemm_issue(smb, 0, 0, a_hi, a_lo, b_hi, b_lo, m0, n0, t);
    CP_COMMIT();
    gemm_issue(smb, 1, 1, a_hi, a_lo, b_hi, b_lo, m0, n0, t);
    CP_COMMIT();

    const int aRow = 32*wm + (lane & 15);
    const int aChk = lane >> 4;
    const int bRowOff = ((lane >> 4) & 1)*8 + (lane & 7);
    const int bChkOff = (lane >> 3) & 1;

    int buf = 0;
    for (int c = 0; c < NCHUNK; c++) {
        if (c < NCHUNK - 1) { CP_WAIT(1); } else { CP_WAIT(0); }
        __syncthreads();
        if (c + 2 < NCHUNK) {
            int nbuf = buf + 2; if (nbuf >= GSTAGES) nbuf -= GSTAGES;
            gemm_issue(smb, nbuf, c + 2, a_hi, a_lo, b_hi, b_lo, m0, n0, t);
            CP_COMMIT();
        }

        uint32_t bAh = smb + buf*GBUF;
        uint32_t bAl = bAh + GT_SZ;
        uint32_t bBh = bAh + 2*GT_SZ;
        uint32_t bBl = bAh + 3*GT_SZ;

#pragma unroll
        for (int j = 0; j < 4; j++) {
            uint32_t ah[2][4], al[2][4];
            ldm_x4(ah[0], bAh + phys(aRow,      2*j + aChk));
            ldm_x4(ah[1], bAh + phys(aRow + 16, 2*j + aChk));
            ldm_x4(al[0], bAl + phys(aRow,      2*j + aChk));
            ldm_x4(al[1], bAl + phys(aRow + 16, 2*j + aChk));
            uint32_t bh[2][4], bl[2][4];
#pragma unroll
            for (int p = 0; p < 2; p++) {
                int br = 32*wn + 16*p + bRowOff;
                ldm_x4(bh[p], bBh + phys(br, 2*j + bChkOff));
                ldm_x4(bl[p], bBl + phys(br, 2*j + bChkOff));
            }
#pragma unroll
            for (int nt = 0; nt < 4; nt++) {
                const uint32_t* Bh = &bh[nt >> 1][(nt & 1)*2];
                const uint32_t* Bl = &bl[nt >> 1][(nt & 1)*2];
#pragma unroll
                for (int mt = 0; mt < 2; mt++) {
                    mma16816(acc[mt][nt], ah[mt], Bh);
                    mma16816(acc[mt][nt], ah[mt], Bl);
                    mma16816(acc[mt][nt], al[mt], Bh);
                }
            }
        }
        buf++; if (buf >= GSTAGES) buf -= GSTAGES;
    }

    // epilogue
#pragma unroll
    for (int nt = 0; nt < 4; nt++) {
        int col2 = n0 + 32*wn + 8*nt + 2*(lane & 3);
        float2 bb = *reinterpret_cast<const float2*>(bias + col2);
#pragma unroll
        for (int mt = 0; mt < 2; mt++) {
            int row0 = m0 + 32*wm + 16*mt + (lane >> 2);
            int row1 = row0 + 8;
            float v00 = acc[mt][nt][0] + bb.x, v01 = acc[mt][nt][1] + bb.y;
            float v10 = acc[mt][nt][2] + bb.x, v11 = acc[mt][nt][3] + bb.y;
            if (outf) {
                *reinterpret_cast<float2*>(outf + (size_t)row0*DMODEL + col2) = make_float2(v00, v01);
                *reinterpret_cast<float2*>(outf + (size_t)row1*DMODEL + col2) = make_float2(v10, v11);
            } else {
                uint32_t h0 = pack_bf16x2(v00, v01);
                uint32_t l0 = pack_bf16x2(v00 - bf16lo_f(h0), v01 - bf16hi_f(h0));
                uint32_t h1 = pack_bf16x2(v10, v11);
                uint32_t l1 = pack_bf16x2(v10 - bf16lo_f(h1), v11 - bf16hi_f(h1));
                *reinterpret_cast<uint32_t*>(dhi + (size_t)row0*DMODEL + col2) = h0;
                *reinterpret_cast<uint32_t*>(dlo + (size_t)row0*DMODEL + col2) = l0;
                *reinterpret_cast<uint32_t*>(dhi + (size_t)row1*DMODEL + col2) = h1;
                *reinterpret_cast<uint32_t*>(dlo + (size_t)row1*DMODEL + col2) = l1;
            }
        }
    }
}

__global__ __launch_bounds__(GEMM_THREADS, 1)
void gemm_qkv_kernel(const float* __restrict__ bq,
                     const float* __restrict__ bk,
                     const float* __restrict__ bv)
{
    const int z = blockIdx.z;
    const __nv_bfloat16* ah = (z == 0) ? g_q_hi : (z == 1) ? g_k_hi : g_v_hi;
    const __nv_bfloat16* al = (z == 0) ? g_q_lo : (z == 1) ? g_k_lo : g_v_lo;
    const __nv_bfloat16* bh = g_wt_hi + (size_t)z*DMODEL*DMODEL;
    const __nv_bfloat16* bl = g_wt_lo + (size_t)z*DMODEL*DMODEL;
    const float* bias = (z == 0) ? bq : (z == 1) ? bk : bv;
    __nv_bfloat16* dh = (z == 0) ? g_qp_hi : (z == 1) ? g_kp_hi : g_vp_hi;
    __nv_bfloat16* dl = (z == 0) ? g_qp_lo : (z == 1) ? g_kp_lo : g_vp_lo;
    gemm_body(ah, al, bh, bl, bias, dh, dl, nullptr);
}

__global__ __launch_bounds__(GEMM_THREADS, 1)
void gemm_o_kernel(const float* __restrict__ bo, float* __restrict__ out)
{
    gemm_body(g_ctx_hi, g_ctx_lo,
              g_wt_hi + (size_t)3*DMODEL*DMODEL, g_wt_lo + (size_t)3*DMODEL*DMODEL,
              bo, nullptr, nullptr, out);
}

// ---------------- flash attention via mma.sync ----------------
// CTA: 8 warps, BQ=128 (16 q-rows per warp), BK=64 per iteration, 2 CTAs/SM.
#define AT_SZ    8192                  // one 64x64 bf16 tile
#define QT_SZ    16384                 // 128x64 bf16 tile
#define OFF_QH   0
#define OFF_QL   (QT_SZ)
#define OFF_KV(b) (2*QT_SZ + (b)*4*AT_SZ)
#define ASMEM    (2*QT_SZ + 2*4*AT_SZ) // 98304

__device__ __forceinline__ void attn_issue_kv(uint32_t smb, int buf, int kb,
                                              const __nv_bfloat16* kh,
                                              const __nv_bfloat16* kl,
                                              const __nv_bfloat16* vh,
                                              const __nv_bfloat16* vl,
                                              int t)
{
    const int lr  = t >> 2;            // 0..63
    const int lc0 = (t & 3) << 1;      // {0,2,4,6}
    size_t srow = (size_t)(kb*64 + lr) * DMODEL;
    uint32_t base = smb + OFF_KV(buf);
#pragma unroll
    for (int i = 0; i < 2; i++) {
        int ch = lc0 + i;
        int po = phys(lr, ch);
        CPASYNC16(base + 0*AT_SZ + po, kh + srow + ch*8);
        CPASYNC16(base + 1*AT_SZ + po, kl + srow + ch*8);
        CPASYNC16(base + 2*AT_SZ + po, vh + srow + ch*8);
        CPASYNC16(base + 3*AT_SZ + po, vl + srow + ch*8);
    }
}

__global__ __launch_bounds__(256, 2)
void attn_kernel()
{
    extern __shared__ char sm[];
    const uint32_t smb = smem_u32(sm);
    const int t = threadIdx.x;
    const int w = t >> 5, lane = t & 31;
    const int b = blockIdx.y >> 4, h = blockIdx.y & 15;
    const int q0 = blockIdx.x * 128;
    const float inv = 1.0f / (sqrtf(64.0f) + 1e-8f);

    const size_t hoff = (size_t)h * HDIM;
    const __nv_bfloat16* qh_g = g_qp_hi + ((size_t)(b*SEQ + q0))*DMODEL + hoff;
    const __nv_bfloat16* ql_g = g_qp_lo + ((size_t)(b*SEQ + q0))*DMODEL + hoff;
    const __nv_bfloat16* kh_g = g_kp_hi + ((size_t)(b*SEQ))*DMODEL + hoff;
    const __nv_bfloat16* kl_g = g_kp_lo + ((size_t)(b*SEQ))*DMODEL + hoff;
    const __nv_bfloat16* vh_g = g_vp_hi + ((size_t)(b*SEQ))*DMODEL + hoff;
    const __nv_bfloat16* vl_g = g_vp_lo + ((size_t)(b*SEQ))*DMODEL + hoff;

    // prologue: Q tiles (128 rows) + KV tile 0
    {
        const int lr  = t >> 1;        // 0..127
        const int lc0 = (t & 1) << 2;  // {0,4}
        size_t srow = (size_t)lr * DMODEL;
#pragma unroll
        for (int i = 0; i < 4; i++) {
            int ch = lc0 + i;
            int po = phys(lr, ch);
            CPASYNC16(smb + OFF_QH + po, qh_g + srow + ch*8);
            CPASYNC16(smb + OFF_QL + po, ql_g + srow + ch*8);
        }
        attn_issue_kv(smb, 0, 0, kh_g, kl_g, vh_g, vl_g, t);
        CP_COMMIT();
    }

    uint32_t qh[4][4], ql[4][4];
    float o[8][4];
#pragma unroll
    for (int nt = 0; nt < 8; nt++)
#pragma unroll
        for (int c = 0; c < 4; c++) o[nt][c] = 0.f;
    float m0v = -1e30f, m1v = -1e30f, l0v = 0.f, l1v = 0.f;

    const int r0g = q0 + 16*w + (lane >> 2);   // global q row (low)
    const uint32_t* mbase0 = g_maskbits + ((size_t)b*SEQ + r0g)*MWORDS;
    const uint32_t* mbase1 = mbase0 + 8*MWORDS;

    const int aRow = 16*w + (lane & 15);
    const int aChk = lane >> 4;
    // x4 K addressing: rows 8*(ntp*2 + (lane>>4)) + (lane&7), chunk 2j+((lane>>3)&1)
    const int kRow4 = ((lane >> 4) << 3) + (lane & 7);
    const int kChk4 = (lane >> 3) & 1;
    // x4t V addressing: rows 16j + (lane&15), chunk 2*ntp + (lane>>4)
    const int vRow4 = lane & 15;
    const int vSel4 = lane >> 4;

    for (int kb = 0; kb < SEQ/64; kb++) {
        const int buf = kb & 1;
        if (kb + 1 < SEQ/64) {
            attn_issue_kv(smb, buf ^ 1, kb + 1, kh_g, kl_g, vh_g, vl_g, t);
            CP_COMMIT();
            CP_WAIT(1);
        } else {
            CP_WAIT(0);
        }
        __syncthreads();

        if (kb == 0) {
#pragma unroll
            for (int j = 0; j < 4; j++) {
                ldm_x4(qh[j], smb + OFF_QH + phys(aRow, 2*j + aChk));
                ldm_x4(ql[j], smb + OFF_QL + phys(aRow, 2*j + aChk));
            }
        }

        uint32_t bKh = smb + OFF_KV(buf);
        uint32_t bKl = bKh + AT_SZ;
        uint32_t bVh = bKh + 2*AT_SZ;
        uint32_t bVl = bKh + 3*AT_SZ;

        // ---- S = Q K^T (3-term split), K frags via ldmatrix.x4 (2 n-tiles)
        float s[8][4];
#pragma unroll
        for (int nt = 0; nt < 8; nt++)
#pragma unroll
            for (int c = 0; c < 4; c++) s[nt][c] = 0.f;

#pragma unroll
        for (int j = 0; j < 4; j++) {
#pragma unroll
            for (int ntp = 0; ntp < 4; ntp++) {
                uint32_t bh4[4], bl4[4];
                ldm_x4(bh4, bKh + phys(16*ntp + kRow4, 2*j + kChk4));
                ldm_x4(bl4, bKl + phys(16*ntp + kRow4, 2*j + kChk4));
                mma16816(s[2*ntp],   qh[j], &bh4[0]);
                mma16816(s[2*ntp],   qh[j], &bl4[0]);
                mma16816(s[2*ntp],   ql[j], &bh4[0]);
                mma16816(s[2*ntp+1], qh[j], &bh4[2]);
                mma16816(s[2*ntp+1], qh[j], &bl4[2]);
                mma16816(s[2*ntp+1], ql[j], &bh4[2]);
            }
        }

        // ---- mask + scale (exact reference semantics: -1e9 on masked)
        const int kw = (kb*64) >> 5;
        uint32_t w00 = mbase0[kw], w01 = mbase0[kw+1];
        uint32_t w10 = mbase1[kw], w11 = mbase1[kw+1];
#pragma unroll
        for (int nt = 0; nt < 8; nt++) {
            int nl = 8*nt + 2*(lane & 3);
            uint32_t wr0 = (nl & 32) ? w01 : w00;
            uint32_t wr1 = (nl & 32) ? w11 : w10;
            int sh = nl & 31;
            s[nt][0] = ((wr0 >> sh) & 1)       ? -1e9f : s[nt][0]*inv;
            s[nt][1] = ((wr0 >> (sh+1)) & 1)   ? -1e9f : s[nt][1]*inv;
            s[nt][2] = ((wr1 >> sh) & 1)       ? -1e9f : s[nt][2]*inv;
            s[nt][3] = ((wr1 >> (sh+1)) & 1)   ? -1e9f : s[nt][3]*inv;
        }

        // ---- online softmax (rows r0g, r0g+8 per thread)
        float mx0 = -1e30f, mx1 = -1e30f;
#pragma unroll
        for (int nt = 0; nt < 8; nt++) {
            mx0 = fmaxf(mx0, fmaxf(s[nt][0], s[nt][1]));
            mx1 = fmaxf(mx1, fmaxf(s[nt][2], s[nt][3]));
        }
        mx0 = fmaxf(mx0, __shfl_xor_sync(0xffffffffu, mx0, 1));
        mx0 = fmaxf(mx0, __shfl_xor_sync(0xffffffffu, mx0, 2));
        mx1 = fmaxf(mx1, __shfl_xor_sync(0xffffffffu, mx1, 1));
        mx1 = fmaxf(mx1, __shfl_xor_sync(0xffffffffu, mx1, 2));

        float mn0 = fmaxf(m0v, mx0), mn1 = fmaxf(m1v, mx1);
        float al0 = __expf(m0v - mn0), al1 = __expf(m1v - mn1);
        m0v = mn0; m1v = mn1;

        float ls0 = 0.f, ls1 = 0.f;
#pragma unroll
        for (int nt = 0; nt < 8; nt++) {
            s[nt][0] = __expf(s[nt][0] - mn0);
            s[nt][1] = __expf(s[nt][1] - mn0);
            s[nt][2] = __expf(s[nt][2] - mn1);
            s[nt][3] = __expf(s[nt][3] - mn1);
            ls0 += s[nt][0] + s[nt][1];
            ls1 += s[nt][2] + s[nt][3];
        }
        ls0 += __shfl_xor_sync(0xffffffffu, ls0, 1);
        ls0 += __shfl_xor_sync(0xffffffffu, ls0, 2);
        ls1 += __shfl_xor_sync(0xffffffffu, ls1, 1);
        ls1 += __shfl_xor_sync(0xffffffffu, ls1, 2);
        l0v = l0v*al0 + ls0;
        l1v = l1v*al1 + ls1;

#pragma unroll
        for (int nt = 0; nt < 8; nt++) {
            o[nt][0] *= al0; o[nt][1] *= al0;
            o[nt][2] *= al1; o[nt][3] *= al1;
        }

        // ---- O += P V (P split hi/lo; V via ldmatrix.x4.trans: 2 n-chunks)
#pragma unroll
        for (int j = 0; j < 4; j++) {
            uint32_t ph[4], pl[4];
            float e0, e1;
            e0 = s[2*j][0];   e1 = s[2*j][1];
            ph[0] = pack_bf16x2(e0, e1);
            pl[0] = pack_bf16x2(e0 - bf16lo_f(ph[0]), e1 - bf16hi_f(ph[0]));
            e0 = s[2*j][2];   e1 = s[2*j][3];
            ph[1] = pack_bf16x2(e0, e1);
            pl[1] = pack_bf16x2(e0 - bf16lo_f(ph[1]), e1 - bf16hi_f(ph[1]));
            e0 = s[2*j+1][0]; e1 = s[2*j+1][1];
            ph[2] = pack_bf16x2(e0, e1);
            pl[2] = pack_bf16x2(e0 - bf16lo_f(ph[2]), e1 - bf16hi_f(ph[2]));
            e0 = s[2*j+1][2]; e1 = s[2*j+1][3];
            ph[3] = pack_bf16x2(e0, e1);
            pl[3] = pack_bf16x2(e0 - bf16lo_f(ph[3]), e1 - bf16hi_f(ph[3]));
#pragma unroll
            for (int ntp = 0; ntp < 4; ntp++) {
                uint32_t vh4[4], vl4[4];
                ldm_x4t(vh4, bVh + phys(16*j + vRow4, 2*ntp + vSel4));
                ldm_x4t(vl4, bVl + phys(16*j + vRow4, 2*ntp + vSel4));
                mma16816(o[2*ntp],   ph, &vh4[0]);
                mma16816(o[2*ntp],   ph, &vl4[0]);
                mma16816(o[2*ntp],   pl, &vh4[0]);
                mma16816(o[2*ntp+1], ph, &vh4[2]);
                mma16816(o[2*ntp+1], ph, &vl4[2]);
                mma16816(o[2*ntp+1], pl, &vh4[2]);
            }
        }
        __syncthreads();
    }

    // ---- finalize: ctx = O / l, write bf16 hi/lo
    float il0 = 1.f / l0v, il1 = 1.f / l1v;
    const size_t row0 = (size_t)(b*SEQ + r0g);
    const size_t row1 = row0 + 8;
#pragma unroll
    for (int nt = 0; nt < 8; nt++) {
        int col = h*64 + 8*nt + 2*(lane & 3);
        float v00 = o[nt][0]*il0, v01 = o[nt][1]*il0;
        float v10 = o[nt][2]*il1, v11 = o[nt][3]*il1;
        uint32_t h0 = pack_bf16x2(v00, v01);
        uint32_t l0 = pack_bf16x2(v00 - bf16lo_f(h0), v01 - bf16hi_f(h0));
        uint32_t h1 = pack_bf16x2(v10, v11);
        uint32_t l1 = pack_bf16x2(v10 - bf16lo_f(h1), v11 - bf16hi_f(h1));
        *reinterpret_cast<uint32_t*>(g_ctx_hi + row0*DMODEL + col) = h0;
        *reinterpret_cast<uint32_t*>(g_ctx_lo + row0*DMODEL + col) = l0;
        *reinterpret_cast<uint32_t*>(g_ctx_hi + row1*DMODEL + col) = h1;
        *reinterpret_cast<uint32_t*>(g_ctx_lo + row1*DMODEL + col) = l1;
    }
}

// ---------------------------------------------------------------------------
extern "C" void kernel_launch(void* const* d_in, const int* in_sizes, int n_in,
                              void* d_out, int out_size)
{
    const float* q    = (const float*)d_in[0];
    const float* k    = (const float*)d_in[1];
    const float* v    = (const float*)d_in[2];
    const int*   mask = (const int*)  d_in[3];
    const float* wq   = (const float*)d_in[4];
    const float* bq   = (const float*)d_in[5];
    const float* wk   = (const float*)d_in[6];
    const float* bk   = (const float*)d_in[7];
    const float* wv   = (const float*)d_in[8];
    const float* bv   = (const float*)d_in[9];
    const float* wo   = (const float*)d_in[10];
    const float* bo   = (const float*)d_in[11];
    float* out = (float*)d_out;

    cudaFuncSetAttribute(gemm_qkv_kernel,
                         cudaFuncAttributeMaxDynamicSharedMemorySize, GSMEM);
    cudaFuncSetAttribute(gemm_o_kernel,
                         cudaFuncAttributeMaxDynamicSharedMemorySize, GSMEM);
    cudaFuncSetAttribute(attn_kernel,
                         cudaFuncAttributeMaxDynamicSharedMemorySize, ASMEM);

    // prep
    dim3 gc(MTOT*DMODEL/4/256, 3);
    cvt_inputs_kernel<<<gc, 256>>>(q, k, v);
    dim3 gw(DMODEL/32, DMODEL/32, 4);
    cvt_w_kernel<<<gw, dim3(32, 8)>>>(wq, wk, wv, wo);
    maskbits_kernel<<<BATCH*SEQ*SEQ/256, 256>>>(mask);

    // qkv projections
    dim3 gg(DMODEL/128, MTOT/128, 3);
    gemm_qkv_kernel<<<gg, GEMM_THREADS, GSMEM>>>(bq, bk, bv);

    // attention
    dim3 ga(SEQ/128, BATCH*NHEAD);
    attn_kernel<<<ga, 256, ASMEM>>>();

    // output projection
    dim3 go(DMODEL/128, MTOT/128, 1);
    gemm_o_kernel<<<go, GEMM_THREADS, GSMEM>>>(bo, out);
}